// round 11
// baseline (speedup 1.0000x reference)
#include <cuda_runtime.h>
#include <cuda_bf16.h>
#include <math.h>

#define B_      8
#define S_      2048
#define D_      320
#define NH_     5
#define HD_     64
#define FF_     864
#define NL_     6
#define NLOOPS_ 8
#define TOK_    (B_*S_)          // 16384
#define KSEL_   1638             // int(2048*0.8)
#define QKVW_   (3*D_)           // 960
#define KPMAX_  896

typedef unsigned int       u32;
typedef unsigned long long u64;
typedef unsigned long long ull;

// ---------------- f32x2 packed helpers (attention) ---------------------------
__device__ __forceinline__ ull pk2(float x, float y) {
    ull r; asm("mov.b64 %0,{%1,%2};" : "=l"(r) : "f"(x), "f"(y)); return r;
}
__device__ __forceinline__ float2 upk(ull v) {
    float2 f; asm("mov.b64 {%0,%1},%2;" : "=f"(f.x), "=f"(f.y) : "l"(v)); return f;
}
__device__ __forceinline__ ull fma2(ull a, ull b, ull c) {
    ull d; asm("fma.rn.f32x2 %0,%1,%2,%3;" : "=l"(d) : "l"(a), "l"(b), "l"(c)); return d;
}
__device__ __forceinline__ ull mul2(ull a, ull b) {
    ull d; asm("mul.rn.f32x2 %0,%1,%2;" : "=l"(d) : "l"(a), "l"(b)); return d;
}
__device__ __forceinline__ ull add2(ull a, ull b) {
    ull d; asm("add.rn.f32x2 %0,%1,%2;" : "=l"(d) : "l"(a), "l"(b)); return d;
}

// ---------------- mma.sync / cp.async helpers --------------------------------
__device__ __forceinline__ u32 s2u(const void* p) {
    u32 a;
    asm("{ .reg .u64 t; cvta.to.shared.u64 t, %1; cvt.u32.u64 %0, t; }" : "=r"(a) : "l"(p));
    return a;
}
__device__ __forceinline__ void ldsm4(u32& r0, u32& r1, u32& r2, u32& r3, u32 addr) {
    asm volatile("ldmatrix.sync.aligned.m8n8.x4.shared.b16 {%0,%1,%2,%3},[%4];"
                 : "=r"(r0), "=r"(r1), "=r"(r2), "=r"(r3) : "r"(addr));
}
__device__ __forceinline__ void mma16816(float* c, const u32* a, u32 b0, u32 b1) {
    asm volatile(
        "mma.sync.aligned.m16n8k16.row.col.f32.bf16.bf16.f32 "
        "{%0,%1,%2,%3},{%4,%5,%6,%7},{%8,%9},{%0,%1,%2,%3};"
        : "+f"(c[0]), "+f"(c[1]), "+f"(c[2]), "+f"(c[3])
        : "r"(a[0]), "r"(a[1]), "r"(a[2]), "r"(a[3]), "r"(b0), "r"(b1));
}
__device__ __forceinline__ void cpa16(u32 s, const void* g, u32 src_bytes) {
    asm volatile("cp.async.cg.shared.global [%0],[%1],16,%2;"
                 :: "r"(s), "l"(g), "r"(src_bytes));
}
__device__ __forceinline__ void cpa_commit() {
    asm volatile("cp.async.commit_group;");
}
__device__ __forceinline__ void cpa_wait0() {
    asm volatile("cp.async.wait_group 0;");
}

// ---------------- scratch (device globals; no allocations allowed) ----------
static __device__ float g_X[TOK_*D_];                    // residual stream
static __device__ float g_QKV[TOK_*QKVW_];               // qkv projections
static __device__ float g_T1[TOK_*FF_];                  // gate pre-activation
static __device__ float g_RS[TOK_];                      // mask*prob per token
static __device__ float g_P[TOK_];                       // router probs
static __device__ __nv_bfloat16 g_Ahi[(size_t)TOK_*D_];  // activation hi (stride D_)
static __device__ __nv_bfloat16 g_Alo[(size_t)TOK_*D_];
static __device__ __nv_bfloat16 g_Ghi[(size_t)TOK_*FF_]; // mlp intermediate hi
static __device__ __nv_bfloat16 g_Glo[(size_t)TOK_*FF_];
static __device__ __nv_bfloat16 g_Whi[QKVW_*KPMAX_];
static __device__ __nv_bfloat16 g_Wlo[QKVW_*KPMAX_];

__device__ __forceinline__ void split_store(__nv_bfloat16* hi, __nv_bfloat16* lo,
                                            float v) {
    __nv_bfloat16 h = __float2bfloat16(v);
    *hi = h;
    *lo = __float2bfloat16(v - __bfloat162float(h));
}
__device__ __forceinline__ __nv_bfloat162 sp2hi(float a, float b) {
    return __nv_bfloat162(__float2bfloat16(a), __float2bfloat16(b));
}
__device__ __forceinline__ __nv_bfloat162 sp2lo(float a, float b) {
    __nv_bfloat16 ha = __float2bfloat16(a), hb = __float2bfloat16(b);
    return __nv_bfloat162(__float2bfloat16(a - __bfloat162float(ha)),
                          __float2bfloat16(b - __bfloat162float(hb)));
}

// ---------------- embedding + iter_emb --------------------------------------
__global__ void embed_kernel(const int* __restrict__ ids, const int* __restrict__ iter,
                             const float* __restrict__ emb, const float* __restrict__ iemb)
{
    int t = blockIdx.x;
    int id = ids[t];
    int it = iter[0];
    const float* e = emb + (size_t)id * D_;
    const float* a = (it >= 0 && it < NLOOPS_) ? (iemb + (size_t)it * D_) : nullptr;
    for (int d = threadIdx.x; d < D_; d += blockDim.x) {
        float v = e[d];
        if (a) v += a[d];
        g_X[(size_t)t * D_ + d] = v;
    }
}

// ------ rmsnorm fused with bf16 hi/lo split -> g_Ahi/g_Alo -------------------
__global__ __launch_bounds__(128) void rmsnorm_kernel(const float* __restrict__ w,
                                                      float* __restrict__ outp)
{
    int t = blockIdx.x;
    const float* x = g_X + (size_t)t * D_;
    float s = 0.f;
    for (int d = threadIdx.x; d < D_; d += 128) { float v = x[d]; s = fmaf(v, v, s); }
    #pragma unroll
    for (int o = 16; o > 0; o >>= 1) s += __shfl_xor_sync(0xffffffffu, s, o);
    __shared__ float red[4];
    if ((threadIdx.x & 31) == 0) red[threadIdx.x >> 5] = s;
    __syncthreads();
    s = red[0] + red[1] + red[2] + red[3];
    float inv = rsqrtf(s * (1.f / D_) + 1e-6f);
    if (outp) {
        float* dst = outp + (size_t)t * D_;
        for (int d = threadIdx.x; d < D_; d += 128) dst[d] = w[d] * x[d] * inv;
    } else {
        __nv_bfloat16* hi = g_Ahi + (size_t)t * D_;
        __nv_bfloat16* lo = g_Alo + (size_t)t * D_;
        for (int d = threadIdx.x; d < D_; d += 128)
            split_store(hi + d, lo + d, w[d] * x[d] * inv);
    }
}

// ---------------- weight fp32 -> bf16 hi/lo ----------------------------------
__global__ __launch_bounds__(128) void conv_w_kernel(const float* __restrict__ W, int K)
{
    int n = blockIdx.x;
    const float* s = W + (size_t)n * K;
    __nv_bfloat16* hi = g_Whi + (size_t)n * K;
    __nv_bfloat16* lo = g_Wlo + (size_t)n * K;
    for (int d = threadIdx.x; d < K; d += 128)
        split_store(hi + d, lo + d, s[d]);
}

// ====== HMMA bf16-split GEMM, cp.async 2-stage pipeline =====================
#define AST_    40
#define AH_SZ   (128*AST_*2)     // 10240 bytes
#define BH_SZ   (64*AST_*2)      // 5120 bytes
#define BUF_SZ  (2*AH_SZ + 2*BH_SZ)   // 30720
#define SMEM_MM (2*BUF_SZ)            // 61440

__global__ __launch_bounds__(256, 2) void mma_gemm_kernel(int N, int Kp, int nch,
                                                          int mode, int csel, int asel)
{
    extern __shared__ char dsm[];
    u32 sb = s2u(dsm);
    int tid = threadIdx.x, lane = tid & 31, wid = tid >> 5;
    int n0 = blockIdx.x * 64, m0 = blockIdx.y * 128;
    int mbase = (wid >> 1) * 32;
    int nbase = (wid & 1) * 32;

    const __nv_bfloat16* Ahi = asel ? g_Ghi : g_Ahi;
    const __nv_bfloat16* Alo = asel ? g_Glo : g_Alo;

    int arow0 = tid >> 2, asec = tid & 3;
    int brow = tid >> 2, bsec = tid & 3;
    u32 a_sof = (u32)(arow0 * AST_ + asec * 8) * 2;
    u32 b_sof = (u32)(brow * AST_ + bsec * 8) * 2;
    bool bok = (n0 + brow) < N;
    size_t a_go0 = (size_t)(m0 + arow0) * Kp + asec * 8;
    size_t a_go1 = (size_t)(m0 + arow0 + 64) * Kp + asec * 8;
    size_t b_go  = (size_t)(bok ? (n0 + brow) : 0) * Kp + bsec * 8;
    u32 bbytes = bok ? 16u : 0u;

    u32 adA[2][2], adB[2][2];
    #pragma unroll
    for (int mt = 0; mt < 2; mt++)
        #pragma unroll
        for (int ks = 0; ks < 2; ks++)
            adA[mt][ks] = (u32)((mbase + mt * 16 + (lane & 15)) * AST_ +
                                ks * 16 + (lane >> 4) * 8) * 2;
    #pragma unroll
    for (int pr = 0; pr < 2; pr++)
        #pragma unroll
        for (int ks = 0; ks < 2; ks++) {
            int sel = lane >> 3;
            int nr = nbase + pr * 16 + (sel >> 1) * 8 + (lane & 7);
            int kc = ks * 16 + (sel & 1) * 8;
            adB[pr][ks] = (u32)(nr * AST_ + kc) * 2;
        }

    float acc[2][4][4];
    #pragma unroll
    for (int mt = 0; mt < 2; mt++)
        #pragma unroll
        for (int nt = 0; nt < 4; nt++)
            #pragma unroll
            for (int q = 0; q < 4; q++) acc[mt][nt][q] = 0.f;

    {
        u32 bb = sb;
        cpa16(bb + a_sof, Ahi + a_go0, 16);
        cpa16(bb + a_sof + (u32)(64 * AST_ * 2), Ahi + a_go1, 16);
        cpa16(bb + AH_SZ + a_sof, Alo + a_go0, 16);
        cpa16(bb + AH_SZ + a_sof + (u32)(64 * AST_ * 2), Alo + a_go1, 16);
        cpa16(bb + 2 * AH_SZ + b_sof, g_Whi + b_go, bbytes);
        cpa16(bb + 2 * AH_SZ + BH_SZ + b_sof, g_Wlo + b_go, bbytes);
        cpa_commit();
    }

    for (int c = 0; c < nch; c++) {
        cpa_wait0();
        __syncthreads();
        if (c + 1 < nch) {
            int ko = (c + 1) * 32;
            u32 bb = sb + ((c + 1) & 1) * BUF_SZ;
            cpa16(bb + a_sof, Ahi + a_go0 + ko, 16);
            cpa16(bb + a_sof + (u32)(64 * AST_ * 2), Ahi + a_go1 + ko, 16);
            cpa16(bb + AH_SZ + a_sof, Alo + a_go0 + ko, 16);
            cpa16(bb + AH_SZ + a_sof + (u32)(64 * AST_ * 2), Alo + a_go1 + ko, 16);
            cpa16(bb + 2 * AH_SZ + b_sof, g_Whi + b_go + ko, bbytes);
            cpa16(bb + 2 * AH_SZ + BH_SZ + b_sof, g_Wlo + b_go + ko, bbytes);
            cpa_commit();
        }
        u32 bb = sb + (c & 1) * BUF_SZ;
        u32 baA = bb, baAl = bb + AH_SZ;
        u32 baB = bb + 2 * AH_SZ, baBl = bb + 2 * AH_SZ + BH_SZ;
        #pragma unroll
        for (int ks = 0; ks < 2; ks++) {
            u32 ah[2][4], al[2][4], bh[2][4], bl[2][4];
            #pragma unroll
            for (int mt = 0; mt < 2; mt++) {
                ldsm4(ah[mt][0], ah[mt][1], ah[mt][2], ah[mt][3], baA + adA[mt][ks]);
                ldsm4(al[mt][0], al[mt][1], al[mt][2], al[mt][3], baAl + adA[mt][ks]);
            }
            #pragma unroll
            for (int pr = 0; pr < 2; pr++) {
                ldsm4(bh[pr][0], bh[pr][1], bh[pr][2], bh[pr][3], baB + adB[pr][ks]);
                ldsm4(bl[pr][0], bl[pr][1], bl[pr][2], bl[pr][3], baBl + adB[pr][ks]);
            }
            #pragma unroll
            for (int mt = 0; mt < 2; mt++)
                #pragma unroll
                for (int nt = 0; nt < 4; nt++) {
                    int pr = nt >> 1, of = (nt & 1) * 2;
                    mma16816(acc[mt][nt], ah[mt], bh[pr][of], bh[pr][of + 1]);
                    mma16816(acc[mt][nt], ah[mt], bl[pr][of], bl[pr][of + 1]);
                    mma16816(acc[mt][nt], al[mt], bh[pr][of], bh[pr][of + 1]);
                }
        }
    }

    // epilogue
    int grp = lane >> 2, tg = lane & 3;
    float* C = (csel == 0) ? g_QKV : (csel == 1) ? g_X : g_T1;
    #pragma unroll
    for (int mt = 0; mt < 2; mt++) {
        int r0 = m0 + mbase + mt * 16 + grp;
        int r1 = r0 + 8;
        float rs0 = 1.f, rs1 = 1.f;
        if (mode == 2) { rs0 = g_RS[r0]; rs1 = g_RS[r1]; }
        #pragma unroll
        for (int nt = 0; nt < 4; nt++) {
            int nc = n0 + nbase + nt * 8 + tg * 2;
            if (nc >= N) continue;
            float a0 = acc[mt][nt][0], a1 = acc[mt][nt][1];
            float a2 = acc[mt][nt][2], a3 = acc[mt][nt][3];
            if (mode == 3) {
                const float* t0 = g_T1 + (size_t)r0 * N + nc;
                const float* t1 = g_T1 + (size_t)r1 * N + nc;
                float2 g0 = *(const float2*)t0, g1 = *(const float2*)t1;
                float v00 = (g0.x / (1.f + __expf(-g0.x))) * a0;
                float v01 = (g0.y / (1.f + __expf(-g0.y))) * a1;
                float v10 = (g1.x / (1.f + __expf(-g1.x))) * a2;
                float v11 = (g1.y / (1.f + __expf(-g1.y))) * a3;
                *(__nv_bfloat162*)(g_Ghi + (size_t)r0 * N + nc) = sp2hi(v00, v01);
                *(__nv_bfloat162*)(g_Glo + (size_t)r0 * N + nc) = sp2lo(v00, v01);
                *(__nv_bfloat162*)(g_Ghi + (size_t)r1 * N + nc) = sp2hi(v10, v11);
                *(__nv_bfloat162*)(g_Glo + (size_t)r1 * N + nc) = sp2lo(v10, v11);
            } else {
                float* p0 = C + (size_t)r0 * N + nc;
                float* p1 = C + (size_t)r1 * N + nc;
                if (mode == 0) {
                    *(float2*)p0 = make_float2(a0, a1);
                    *(float2*)p1 = make_float2(a2, a3);
                } else {
                    float2 o0 = *(const float2*)p0, o1 = *(const float2*)p1;
                    *(float2*)p0 = make_float2(o0.x + rs0 * a0, o0.y + rs0 * a1);
                    *(float2*)p1 = make_float2(o1.x + rs1 * a2, o1.y + rs1 * a3);
                }
            }
        }
    }
}

// ---------------- RoPE in-place on q,k parts of g_QKV ------------------------
__global__ __launch_bounds__(160) void rope_kernel()
{
    int t = blockIdx.x;
    int s = t & (S_ - 1);
    int h = threadIdx.x >> 5;
    int i = threadIdx.x & 31;
    float freq = expf(-((float)(2 * i) / (float)HD_) * 9.210340371976184f);
    float ang = (float)s * freq;
    float sn, cs;
    sincosf(ang, &sn, &cs);
    float* qb = g_QKV + (size_t)t * QKVW_ + h * HD_;
    float q1 = qb[i], q2 = qb[i + 32];
    qb[i]      = q1 * cs - q2 * sn;
    qb[i + 32] = q2 * cs + q1 * sn;
    float* kb = qb + D_;
    float k1 = kb[i], k2 = kb[i + 32];
    kb[i]      = k1 * cs - k2 * sn;
    kb[i + 32] = k2 * cs + k1 * sn;
}

// ------ causal flash attention: lane-pair per query (half-dim split) ---------
// block = 128 thr = 64 queries; even lane dims 0-31, odd lane dims 32-63.
__global__ __launch_bounds__(128) void attn_kernel()
{
    int qb = blockIdx.x, h = blockIdx.y, b = blockIdx.z;
    int tid = threadIdx.x;
    int sq = qb * 64 + (tid >> 1);
    int half = tid & 1;
    const float4* qp = (const float4*)(g_QKV + (size_t)(b * S_ + sq) * QKVW_ +
                                       h * HD_ + half * 32);
    ull q2r[16], o2[16];
    #pragma unroll
    for (int i = 0; i < 8; i++) {
        float4 v = qp[i];
        q2r[2*i+0] = pk2(v.x * 0.125f, v.y * 0.125f);
        q2r[2*i+1] = pk2(v.z * 0.125f, v.w * 0.125f);
    }
    #pragma unroll
    for (int i = 0; i < 16; i++) o2[i] = 0ULL;
    float m = -1e30f, l = 0.f;
    __shared__ __align__(16) float Ks[64 * 64];
    __shared__ __align__(16) float Vs[64 * 64];
    int kend = qb * 64 + 64;
    for (int j0 = 0; j0 < kend; j0 += 64) {
        __syncthreads();
        #pragma unroll
        for (int it = 0; it < 8; it++) {
            int idx = it * 128 + tid;
            int r = idx >> 4, c4 = idx & 15;
            const float4* kv = (const float4*)(g_QKV + (size_t)(b * S_ + j0 + r) * QKVW_ + h * HD_);
            ((float4*)Ks)[idx] = kv[80 + c4];
            ((float4*)Vs)[idx] = kv[160 + c4];
        }
        __syncthreads();
        if (j0 > sq) continue;
        int jm = sq - j0;
        int jend = (jm >= 63) ? 64 : (jm + 1);
        for (int j = 0; j < jend; j++) {
            const ulonglong2* kr = (const ulonglong2*)(Ks + j * 64 + half * 32);
            ull sa = 0ULL, sb2 = 0ULL, sc = 0ULL, sd = 0ULL;
            #pragma unroll
            for (int i = 0; i < 4; i++) {
                ulonglong2 k0 = kr[2*i], k1 = kr[2*i+1];
                sa  = fma2(q2r[4*i+0], k0.x, sa);
                sb2 = fma2(q2r[4*i+1], k0.y, sb2);
                sc  = fma2(q2r[4*i+2], k1.x, sc);
                sd  = fma2(q2r[4*i+3], k1.y, sd);
            }
            float2 sf = upk(add2(add2(sa, sb2), add2(sc, sd)));
            float sh = sf.x + sf.y;
            float s = sh + __shfl_xor_sync(0xffffffffu, sh, 1);
            if (s > m) {
                float c = __expf(m - s);
                m = s; l *= c;
                ull c2 = pk2(c, c);
                #pragma unroll
                for (int i = 0; i < 16; i++) o2[i] = mul2(o2[i], c2);
            }
            float p = __expf(s - m);
            l += p;
            ull p2 = pk2(p, p);
            const ulonglong2* vr = (const ulonglong2*)(Vs + j * 64 + half * 32);
            #pragma unroll
            for (int i = 0; i < 8; i++) {
                ulonglong2 vv = vr[i];
                o2[2*i+0] = fma2(p2, vv.x, o2[2*i+0]);
                o2[2*i+1] = fma2(p2, vv.y, o2[2*i+1]);
            }
        }
    }
    float invl = 1.f / l;
    size_t obase = (size_t)(b * S_ + sq) * D_ + h * HD_ + half * 32;
    __nv_bfloat162* hi2 = (__nv_bfloat162*)(g_Ahi + obase);
    __nv_bfloat162* lo2 = (__nv_bfloat162*)(g_Alo + obase);
    #pragma unroll
    for (int i = 0; i < 16; i++) {
        float2 a = upk(o2[i]);
        float v0 = a.x * invl, v1 = a.y * invl;
        hi2[i] = sp2hi(v0, v1);
        lo2[i] = sp2lo(v0, v1);
    }
}

// ---------------- router: sigmoid(X . router_w) one warp per token -----------
__global__ __launch_bounds__(128) void router_kernel(const float* __restrict__ rw)
{
    int t = blockIdx.x * 4 + (threadIdx.x >> 5);
    int lane = threadIdx.x & 31;
    const float* x = g_X + (size_t)t * D_;
    float s = 0.f;
    for (int d = lane; d < D_; d += 32) s = fmaf(x[d], rw[d], s);
    #pragma unroll
    for (int o = 16; o > 0; o >>= 1) s += __shfl_xor_sync(0xffffffffu, s, o);
    if (lane == 0) g_P[t] = 1.f / (1.f + expf(-s));
}

// ---------------- exact stable top-k selection -> g_RS = mask * prob ---------
__global__ __launch_bounds__(256) void select_kernel()
{
    __shared__ float p[S_];
    int b = blockIdx.x;
    for (int t = threadIdx.x; t < S_; t += 256) p[t] = g_P[b * S_ + t];
    __syncthreads();
    int t = blockIdx.y * 256 + threadIdx.x;
    float pt = p[t];
    int rank = 0;
    for (int j = 0; j < S_; j++) {
        float pj = p[j];
        rank += (pj > pt) ? 1 : ((pj == pt && j < t) ? 1 : 0);
    }
    g_RS[b * S_ + t] = (rank < KSEL_) ? pt : 0.f;
}

// ---------------- driver ------------------------------------------------------
extern "C" void kernel_launch(void* const* d_in, const int* in_sizes, int n_in,
                              void* d_out, int out_size)
{
    const int*   ids          = (const int*)d_in[0];
    const int*   iter         = (const int*)d_in[1];
    const float* emb          = (const float*)d_in[2];
    const float* iemb         = (const float*)d_in[3];
    const float* attn_norm_w  = (const float*)d_in[4];
    const float* Wqkv         = (const float*)d_in[5];
    const float* wo_w         = (const float*)d_in[6];
    const float* router_w     = (const float*)d_in[7];
    const float* mlp_norm_w   = (const float*)d_in[8];
    const float* gate_w       = (const float*)d_in[9];
    const float* up_w         = (const float*)d_in[10];
    const float* down_w       = (const float*)d_in[11];
    const float* final_norm_w = (const float*)d_in[12];
    float* out = (float*)d_out;

    cudaFuncSetAttribute(mma_gemm_kernel,
                         cudaFuncAttributeMaxDynamicSharedMemorySize, SMEM_MM);

    embed_kernel<<<TOK_, 128>>>(ids, iter, emb, iemb);
    for (int l = 0; l < NL_; l++) {
        rmsnorm_kernel<<<TOK_, 128>>>(attn_norm_w + l * D_, nullptr);
        conv_w_kernel<<<QKVW_, 128>>>(Wqkv + (size_t)l * QKVW_ * D_, D_);
        mma_gemm_kernel<<<dim3(15, 128), 256, SMEM_MM>>>(QKVW_, D_, 10, 0, 0, 0);
        rope_kernel<<<TOK_, 160>>>();
        attn_kernel<<<dim3(S_ / 64, NH_, B_), 128>>>();
        conv_w_kernel<<<D_, 128>>>(wo_w + (size_t)l * D_ * D_, D_);
        mma_gemm_kernel<<<dim3(5, 128), 256, SMEM_MM>>>(D_, D_, 10, 1, 1, 0);
        router_kernel<<<TOK_ / 4, 128>>>(router_w + l * D_);
        select_kernel<<<dim3(B_, 8), 256>>>();
        rmsnorm_kernel<<<TOK_, 128>>>(mlp_norm_w + l * D_, nullptr);
        conv_w_kernel<<<FF_, 128>>>(gate_w + (size_t)l * FF_ * D_, D_);
        mma_gemm_kernel<<<dim3(14, 128), 256, SMEM_MM>>>(FF_, D_, 10, 0, 2, 0);
        conv_w_kernel<<<FF_, 128>>>(up_w + (size_t)l * FF_ * D_, D_);
        mma_gemm_kernel<<<dim3(14, 128), 256, SMEM_MM>>>(FF_, D_, 10, 3, 2, 0);
        conv_w_kernel<<<D_, 128>>>(down_w + (size_t)l * D_ * FF_, FF_);
        mma_gemm_kernel<<<dim3(5, 128), 256, SMEM_MM>>>(D_, FF_, 27, 2, 1, 1);
    }
    rmsnorm_kernel<<<TOK_, 128>>>(final_norm_w, out);
}

// round 13
// speedup vs baseline: 1.6759x; 1.6759x over previous
#include <cuda_runtime.h>
#include <cuda_bf16.h>
#include <math.h>

#define B_      8
#define S_      2048
#define D_      320
#define NH_     5
#define HD_     64
#define FF_     864
#define NL_     6
#define NLOOPS_ 8
#define TOK_    (B_*S_)          // 16384
#define KSEL_   1638             // int(2048*0.8)
#define QKVW_   (3*D_)           // 960
#define KPMAX_  896

typedef unsigned int       u32;
typedef unsigned long long u64;
typedef unsigned long long ull;

// ---------------- helpers -----------------------------------------------------
__device__ __forceinline__ u32 s2u(const void* p) {
    u32 a;
    asm("{ .reg .u64 t; cvta.to.shared.u64 t, %1; cvt.u32.u64 %0, t; }" : "=r"(a) : "l"(p));
    return a;
}
__device__ __forceinline__ void ldsm4(u32& r0, u32& r1, u32& r2, u32& r3, u32 addr) {
    asm volatile("ldmatrix.sync.aligned.m8n8.x4.shared.b16 {%0,%1,%2,%3},[%4];"
                 : "=r"(r0), "=r"(r1), "=r"(r2), "=r"(r3) : "r"(addr));
}
__device__ __forceinline__ void ldsm4t(u32& r0, u32& r1, u32& r2, u32& r3, u32 addr) {
    asm volatile("ldmatrix.sync.aligned.m8n8.x4.trans.shared.b16 {%0,%1,%2,%3},[%4];"
                 : "=r"(r0), "=r"(r1), "=r"(r2), "=r"(r3) : "r"(addr));
}
__device__ __forceinline__ void mma16816(float* c, const u32* a, u32 b0, u32 b1) {
    asm volatile(
        "mma.sync.aligned.m16n8k16.row.col.f32.bf16.bf16.f32 "
        "{%0,%1,%2,%3},{%4,%5,%6,%7},{%8,%9},{%0,%1,%2,%3};"
        : "+f"(c[0]), "+f"(c[1]), "+f"(c[2]), "+f"(c[3])
        : "r"(a[0]), "r"(a[1]), "r"(a[2]), "r"(a[3]), "r"(b0), "r"(b1));
}
__device__ __forceinline__ void cpa16(u32 s, const void* g, u32 src_bytes) {
    asm volatile("cp.async.cg.shared.global [%0],[%1],16,%2;"
                 :: "r"(s), "l"(g), "r"(src_bytes));
}
__device__ __forceinline__ void cpa_commit() { asm volatile("cp.async.commit_group;"); }
__device__ __forceinline__ void cpa_wait0()  { asm volatile("cp.async.wait_group 0;"); }

// ---------------- scratch (device globals) -----------------------------------
static __device__ float g_X[TOK_*D_];
static __device__ float g_QKV[TOK_*QKVW_];
static __device__ float g_T1[TOK_*FF_];
static __device__ float g_RS[TOK_];
static __device__ float g_P[TOK_];
static __device__ __nv_bfloat16 g_Ahi[(size_t)TOK_*D_];
static __device__ __nv_bfloat16 g_Alo[(size_t)TOK_*D_];
static __device__ __nv_bfloat16 g_Ghi[(size_t)TOK_*FF_];
static __device__ __nv_bfloat16 g_Glo[(size_t)TOK_*FF_];
static __device__ __nv_bfloat16 g_Whi[QKVW_*KPMAX_];
static __device__ __nv_bfloat16 g_Wlo[QKVW_*KPMAX_];
static __device__ __nv_bfloat16 g_Qhi[(size_t)TOK_*D_];  // head-major [b,h,s,hd]
static __device__ __nv_bfloat16 g_Qlo[(size_t)TOK_*D_];
static __device__ __nv_bfloat16 g_Khi[(size_t)TOK_*D_];
static __device__ __nv_bfloat16 g_Klo[(size_t)TOK_*D_];
static __device__ __nv_bfloat16 g_Vhi[(size_t)TOK_*D_];
static __device__ __nv_bfloat16 g_Vlo[(size_t)TOK_*D_];

__device__ __forceinline__ void split_store(__nv_bfloat16* hi, __nv_bfloat16* lo, float v) {
    __nv_bfloat16 h = __float2bfloat16(v);
    *hi = h;
    *lo = __float2bfloat16(v - __bfloat162float(h));
}
__device__ __forceinline__ __nv_bfloat162 sp2hi(float a, float b) {
    return __nv_bfloat162(__float2bfloat16(a), __float2bfloat16(b));
}
__device__ __forceinline__ __nv_bfloat162 sp2lo(float a, float b) {
    __nv_bfloat16 ha = __float2bfloat16(a), hb = __float2bfloat16(b);
    return __nv_bfloat162(__float2bfloat16(a - __bfloat162float(ha)),
                          __float2bfloat16(b - __bfloat162float(hb)));
}
__device__ __forceinline__ u32 pkbf(float a, float b) {
    __nv_bfloat162 v = sp2hi(a, b);
    return *(u32*)&v;
}
__device__ __forceinline__ u32 pkbf_lo(float a, float b) {
    __nv_bfloat162 v = sp2lo(a, b);
    return *(u32*)&v;
}

// ---------------- embedding ---------------------------------------------------
__global__ void embed_kernel(const int* __restrict__ ids, const int* __restrict__ iter,
                             const float* __restrict__ emb, const float* __restrict__ iemb)
{
    int t = blockIdx.x;
    int id = ids[t];
    int it = iter[0];
    const float* e = emb + (size_t)id * D_;
    const float* a = (it >= 0 && it < NLOOPS_) ? (iemb + (size_t)it * D_) : nullptr;
    for (int d = threadIdx.x; d < D_; d += blockDim.x) {
        float v = e[d];
        if (a) v += a[d];
        g_X[(size_t)t * D_ + d] = v;
    }
}

// ---------------- rmsnorm (fused bf16 hi/lo out) ------------------------------
__global__ __launch_bounds__(128) void rmsnorm_kernel(const float* __restrict__ w,
                                                      float* __restrict__ outp)
{
    int t = blockIdx.x;
    const float* x = g_X + (size_t)t * D_;
    float s = 0.f;
    for (int d = threadIdx.x; d < D_; d += 128) { float v = x[d]; s = fmaf(v, v, s); }
    #pragma unroll
    for (int o = 16; o > 0; o >>= 1) s += __shfl_xor_sync(0xffffffffu, s, o);
    __shared__ float red[4];
    if ((threadIdx.x & 31) == 0) red[threadIdx.x >> 5] = s;
    __syncthreads();
    s = red[0] + red[1] + red[2] + red[3];
    float inv = rsqrtf(s * (1.f / D_) + 1e-6f);
    if (outp) {
        float* dst = outp + (size_t)t * D_;
        for (int d = threadIdx.x; d < D_; d += 128) dst[d] = w[d] * x[d] * inv;
    } else {
        __nv_bfloat16* hi = g_Ahi + (size_t)t * D_;
        __nv_bfloat16* lo = g_Alo + (size_t)t * D_;
        for (int d = threadIdx.x; d < D_; d += 128)
            split_store(hi + d, lo + d, w[d] * x[d] * inv);
    }
}

// ---------------- weight fp32 -> bf16 hi/lo -----------------------------------
__global__ __launch_bounds__(128) void conv_w_kernel(const float* __restrict__ W, int K)
{
    int n = blockIdx.x;
    const float* s = W + (size_t)n * K;
    __nv_bfloat16* hi = g_Whi + (size_t)n * K;
    __nv_bfloat16* lo = g_Wlo + (size_t)n * K;
    for (int d = threadIdx.x; d < K; d += 128)
        split_store(hi + d, lo + d, s[d]);
}

// ====== HMMA bf16-split GEMM, cp.async 2-stage pipeline ======================
#define AST_    40
#define AH_SZ   (128*AST_*2)
#define BH_SZ   (64*AST_*2)
#define BUF_SZ  (2*AH_SZ + 2*BH_SZ)
#define SMEM_MM (2*BUF_SZ)

__global__ __launch_bounds__(256, 2) void mma_gemm_kernel(int N, int Kp, int nch,
                                                          int mode, int csel, int asel)
{
    extern __shared__ char dsm[];
    u32 sb = s2u(dsm);
    int tid = threadIdx.x, lane = tid & 31, wid = tid >> 5;
    int n0 = blockIdx.x * 64, m0 = blockIdx.y * 128;
    int mbase = (wid >> 1) * 32;
    int nbase = (wid & 1) * 32;

    const __nv_bfloat16* Ahi = asel ? g_Ghi : g_Ahi;
    const __nv_bfloat16* Alo = asel ? g_Glo : g_Alo;

    int arow0 = tid >> 2, asec = tid & 3;
    int brow = tid >> 2, bsec = tid & 3;
    u32 a_sof = (u32)(arow0 * AST_ + asec * 8) * 2;
    u32 b_sof = (u32)(brow * AST_ + bsec * 8) * 2;
    bool bok = (n0 + brow) < N;
    size_t a_go0 = (size_t)(m0 + arow0) * Kp + asec * 8;
    size_t a_go1 = (size_t)(m0 + arow0 + 64) * Kp + asec * 8;
    size_t b_go  = (size_t)(bok ? (n0 + brow) : 0) * Kp + bsec * 8;
    u32 bbytes = bok ? 16u : 0u;

    u32 adA[2][2], adB[2][2];
    #pragma unroll
    for (int mt = 0; mt < 2; mt++)
        #pragma unroll
        for (int ks = 0; ks < 2; ks++)
            adA[mt][ks] = (u32)((mbase + mt * 16 + (lane & 15)) * AST_ +
                                ks * 16 + (lane >> 4) * 8) * 2;
    #pragma unroll
    for (int pr = 0; pr < 2; pr++)
        #pragma unroll
        for (int ks = 0; ks < 2; ks++) {
            int sel = lane >> 3;
            int nr = nbase + pr * 16 + (sel >> 1) * 8 + (lane & 7);
            int kc = ks * 16 + (sel & 1) * 8;
            adB[pr][ks] = (u32)(nr * AST_ + kc) * 2;
        }

    float acc[2][4][4];
    #pragma unroll
    for (int mt = 0; mt < 2; mt++)
        #pragma unroll
        for (int nt = 0; nt < 4; nt++)
            #pragma unroll
            for (int q = 0; q < 4; q++) acc[mt][nt][q] = 0.f;

    {
        u32 bb = sb;
        cpa16(bb + a_sof, Ahi + a_go0, 16);
        cpa16(bb + a_sof + (u32)(64 * AST_ * 2), Ahi + a_go1, 16);
        cpa16(bb + AH_SZ + a_sof, Alo + a_go0, 16);
        cpa16(bb + AH_SZ + a_sof + (u32)(64 * AST_ * 2), Alo + a_go1, 16);
        cpa16(bb + 2 * AH_SZ + b_sof, g_Whi + b_go, bbytes);
        cpa16(bb + 2 * AH_SZ + BH_SZ + b_sof, g_Wlo + b_go, bbytes);
        cpa_commit();
    }

    for (int c = 0; c < nch; c++) {
        cpa_wait0();
        __syncthreads();
        if (c + 1 < nch) {
            int ko = (c + 1) * 32;
            u32 bb = sb + ((c + 1) & 1) * BUF_SZ;
            cpa16(bb + a_sof, Ahi + a_go0 + ko, 16);
            cpa16(bb + a_sof + (u32)(64 * AST_ * 2), Ahi + a_go1 + ko, 16);
            cpa16(bb + AH_SZ + a_sof, Alo + a_go0 + ko, 16);
            cpa16(bb + AH_SZ + a_sof + (u32)(64 * AST_ * 2), Alo + a_go1 + ko, 16);
            cpa16(bb + 2 * AH_SZ + b_sof, g_Whi + b_go + ko, bbytes);
            cpa16(bb + 2 * AH_SZ + BH_SZ + b_sof, g_Wlo + b_go + ko, bbytes);
            cpa_commit();
        }
        u32 bb = sb + (c & 1) * BUF_SZ;
        u32 baA = bb, baAl = bb + AH_SZ;
        u32 baB = bb + 2 * AH_SZ, baBl = bb + 2 * AH_SZ + BH_SZ;
        #pragma unroll
        for (int ks = 0; ks < 2; ks++) {
            u32 ah[2][4], al[2][4], bh[2][4], bl[2][4];
            #pragma unroll
            for (int mt = 0; mt < 2; mt++) {
                ldsm4(ah[mt][0], ah[mt][1], ah[mt][2], ah[mt][3], baA + adA[mt][ks]);
                ldsm4(al[mt][0], al[mt][1], al[mt][2], al[mt][3], baAl + adA[mt][ks]);
            }
            #pragma unroll
            for (int pr = 0; pr < 2; pr++) {
                ldsm4(bh[pr][0], bh[pr][1], bh[pr][2], bh[pr][3], baB + adB[pr][ks]);
                ldsm4(bl[pr][0], bl[pr][1], bl[pr][2], bl[pr][3], baBl + adB[pr][ks]);
            }
            #pragma unroll
            for (int mt = 0; mt < 2; mt++)
                #pragma unroll
                for (int nt = 0; nt < 4; nt++) {
                    int pr = nt >> 1, of = (nt & 1) * 2;
                    mma16816(acc[mt][nt], ah[mt], bh[pr][of], bh[pr][of + 1]);
                    mma16816(acc[mt][nt], ah[mt], bl[pr][of], bl[pr][of + 1]);
                    mma16816(acc[mt][nt], al[mt], bh[pr][of], bh[pr][of + 1]);
                }
        }
    }

    int grp = lane >> 2, tg = lane & 3;
    float* C = (csel == 0) ? g_QKV : (csel == 1) ? g_X : g_T1;
    #pragma unroll
    for (int mt = 0; mt < 2; mt++) {
        int r0 = m0 + mbase + mt * 16 + grp;
        int r1 = r0 + 8;
        float rs0 = 1.f, rs1 = 1.f;
        if (mode == 2) { rs0 = g_RS[r0]; rs1 = g_RS[r1]; }
        #pragma unroll
        for (int nt = 0; nt < 4; nt++) {
            int nc = n0 + nbase + nt * 8 + tg * 2;
            if (nc >= N) continue;
            float a0 = acc[mt][nt][0], a1 = acc[mt][nt][1];
            float a2 = acc[mt][nt][2], a3 = acc[mt][nt][3];
            if (mode == 3) {
                const float* t0 = g_T1 + (size_t)r0 * N + nc;
                const float* t1 = g_T1 + (size_t)r1 * N + nc;
                float2 g0 = *(const float2*)t0, g1 = *(const float2*)t1;
                float v00 = (g0.x / (1.f + __expf(-g0.x))) * a0;
                float v01 = (g0.y / (1.f + __expf(-g0.y))) * a1;
                float v10 = (g1.x / (1.f + __expf(-g1.x))) * a2;
                float v11 = (g1.y / (1.f + __expf(-g1.y))) * a3;
                *(__nv_bfloat162*)(g_Ghi + (size_t)r0 * N + nc) = sp2hi(v00, v01);
                *(__nv_bfloat162*)(g_Glo + (size_t)r0 * N + nc) = sp2lo(v00, v01);
                *(__nv_bfloat162*)(g_Ghi + (size_t)r1 * N + nc) = sp2hi(v10, v11);
                *(__nv_bfloat162*)(g_Glo + (size_t)r1 * N + nc) = sp2lo(v10, v11);
            } else {
                float* p0 = C + (size_t)r0 * N + nc;
                float* p1 = C + (size_t)r1 * N + nc;
                if (mode == 0) {
                    *(float2*)p0 = make_float2(a0, a1);
                    *(float2*)p1 = make_float2(a2, a3);
                } else {
                    float2 o0 = *(const float2*)p0, o1 = *(const float2*)p1;
                    *(float2*)p0 = make_float2(o0.x + rs0 * a0, o0.y + rs0 * a1);
                    *(float2*)p1 = make_float2(o1.x + rs1 * a2, o1.y + rs1 * a3);
                }
            }
        }
    }
}

// ------ RoPE + bf16 hi/lo conversion of Q(x0.125)/K/V, head-major layout -----
__global__ __launch_bounds__(160) void rope_kernel()
{
    int t = blockIdx.x;
    int b = t >> 11, s = t & (S_ - 1);
    int h = threadIdx.x >> 5;
    int i = threadIdx.x & 31;
    float freq = expf(-((float)(2 * i) / (float)HD_) * 9.210340371976184f);
    float ang = (float)s * freq;
    float sn, cs;
    sincosf(ang, &sn, &cs);
    const float* qb = g_QKV + (size_t)t * QKVW_ + h * HD_;
    const float* kb = qb + D_;
    const float* vb = qb + 2 * D_;
    size_t base = ((size_t)(b * NH_ + h) * S_ + s) * HD_;
    float q1 = qb[i], q2 = qb[i + 32];
    float qr1 = (q1 * cs - q2 * sn) * 0.125f;
    float qr2 = (q2 * cs + q1 * sn) * 0.125f;
    split_store(g_Qhi + base + i,      g_Qlo + base + i,      qr1);
    split_store(g_Qhi + base + i + 32, g_Qlo + base + i + 32, qr2);
    float k1 = kb[i], k2 = kb[i + 32];
    split_store(g_Khi + base + i,      g_Klo + base + i,      k1 * cs - k2 * sn);
    split_store(g_Khi + base + i + 32, g_Klo + base + i + 32, k2 * cs + k1 * sn);
    split_store(g_Vhi + base + i,      g_Vlo + base + i,      vb[i]);
    split_store(g_Vhi + base + i + 32, g_Vlo + base + i + 32, vb[i + 32]);
}

// ====== HMMA flash attention: 64q block (4 warps x 16 rows), 64-key tiles ====
#define FST_ 72
__global__ __launch_bounds__(128) void fa_kernel()
{
    __shared__ __nv_bfloat16 Kh[64 * FST_], Kl[64 * FST_];
    __shared__ __nv_bfloat16 Vh[64 * FST_], Vl[64 * FST_];
    int tid = threadIdx.x, lane = tid & 31, wid = tid >> 5;
    int qt = blockIdx.x, h = blockIdx.y, b = blockIdx.z;
    int grp = lane >> 2, tg = lane & 3;
    size_t hrows = (size_t)(b * NH_ + h) * S_;
    int q0 = qt * 64;

    // --- Q fragments (A layout), loaded once from global ---
    u32 qh[4][4], ql[4][4];
    {
        const __nv_bfloat16* Qg = g_Qhi + (hrows + q0 + wid * 16 + grp) * HD_;
        const __nv_bfloat16* Qg2 = g_Qlo + (hrows + q0 + wid * 16 + grp) * HD_;
        #pragma unroll
        for (int ks = 0; ks < 4; ks++) {
            int col = ks * 16 + tg * 2;
            qh[ks][0] = *(const u32*)(Qg + col);
            qh[ks][1] = *(const u32*)(Qg + 8 * HD_ + col);
            qh[ks][2] = *(const u32*)(Qg + col + 8);
            qh[ks][3] = *(const u32*)(Qg + 8 * HD_ + col + 8);
            ql[ks][0] = *(const u32*)(Qg2 + col);
            ql[ks][1] = *(const u32*)(Qg2 + 8 * HD_ + col);
            ql[ks][2] = *(const u32*)(Qg2 + col + 8);
            ql[ks][3] = *(const u32*)(Qg2 + 8 * HD_ + col + 8);
        }
    }

    // --- ldmatrix base addresses ---
    u32 kbase = s2u(Kh), klbase = s2u(Kl), vbase = s2u(Vh), vlbase = s2u(Vl);
    int sel = lane >> 3, wrow = lane & 7;
    u32 adK[4], adV[4];
    #pragma unroll
    for (int pr = 0; pr < 4; pr++) {
        adK[pr] = (u32)((pr * 16 + (sel >> 1) * 8 + wrow) * FST_ + (sel & 1) * 8) * 2;
        adV[pr] = (u32)(((sel & 1) * 8 + wrow) * FST_ + pr * 16 + (sel >> 1) * 8) * 2;
    }

    // --- staging map: per comp, row = tid>>1, 4 chunks of 16B ---
    int srow = tid >> 1;
    u32 soff = (u32)(srow * FST_) * 2 + (u32)(tid & 1) * 64;
    int gcol = (tid & 1) * 32;

    float o[8][4];
    #pragma unroll
    for (int nt = 0; nt < 8; nt++)
        #pragma unroll
        for (int q = 0; q < 4; q++) o[nt][q] = 0.f;
    float m0 = -1e30f, m1 = -1e30f, l0 = 0.f, l1 = 0.f;

    for (int kt = 0; kt <= qt; kt++) {
        int k0 = kt * 64;
        __syncthreads();
        {
            size_t gr = (hrows + k0 + srow) * HD_ + gcol;
            #pragma unroll
            for (int j = 0; j < 4; j++) {
                cpa16(kbase + soff + j * 16, g_Khi + gr + j * 8, 16);
                cpa16(klbase + soff + j * 16, g_Klo + gr + j * 8, 16);
                cpa16(vbase + soff + j * 16, g_Vhi + gr + j * 8, 16);
                cpa16(vlbase + soff + j * 16, g_Vlo + gr + j * 8, 16);
            }
            cpa_commit();
        }
        cpa_wait0();
        __syncthreads();

        // --- S = Q @ K^T (3-pass split) ---
        float s[8][4];
        #pragma unroll
        for (int nt = 0; nt < 8; nt++)
            #pragma unroll
            for (int q = 0; q < 4; q++) s[nt][q] = 0.f;
        #pragma unroll
        for (int ks = 0; ks < 4; ks++) {
            u32 bh[4][4], bl[4][4];
            #pragma unroll
            for (int pr = 0; pr < 4; pr++) {
                ldsm4(bh[pr][0], bh[pr][1], bh[pr][2], bh[pr][3], kbase + adK[pr] + ks * 32);
                ldsm4(bl[pr][0], bl[pr][1], bl[pr][2], bl[pr][3], klbase + adK[pr] + ks * 32);
            }
            #pragma unroll
            for (int nt = 0; nt < 8; nt++) {
                int pr = nt >> 1, of = (nt & 1) * 2;
                mma16816(s[nt], qh[ks], bh[pr][of], bh[pr][of + 1]);
                mma16816(s[nt], qh[ks], bl[pr][of], bl[pr][of + 1]);
                mma16816(s[nt], ql[ks], bh[pr][of], bh[pr][of + 1]);
            }
        }

        // --- causal mask (diagonal tile only) ---
        if (kt == qt) {
            int rlo = wid * 16 + grp, rhi = rlo + 8;
            #pragma unroll
            for (int nt = 0; nt < 8; nt++) {
                int c0 = nt * 8 + tg * 2, c1 = c0 + 1;
                if (c0 > rlo) s[nt][0] = -1e30f;
                if (c1 > rlo) s[nt][1] = -1e30f;
                if (c0 > rhi) s[nt][2] = -1e30f;
                if (c1 > rhi) s[nt][3] = -1e30f;
            }
        }

        // --- online softmax (rows grp / grp+8) ---
        float t0 = -1e30f, t1 = -1e30f;
        #pragma unroll
        for (int nt = 0; nt < 8; nt++) {
            t0 = fmaxf(t0, fmaxf(s[nt][0], s[nt][1]));
            t1 = fmaxf(t1, fmaxf(s[nt][2], s[nt][3]));
        }
        t0 = fmaxf(t0, __shfl_xor_sync(0xffffffffu, t0, 1));
        t0 = fmaxf(t0, __shfl_xor_sync(0xffffffffu, t0, 2));
        t1 = fmaxf(t1, __shfl_xor_sync(0xffffffffu, t1, 1));
        t1 = fmaxf(t1, __shfl_xor_sync(0xffffffffu, t1, 2));
        float nm0 = fmaxf(m0, t0), nm1 = fmaxf(m1, t1);
        float sc0 = __expf(m0 - nm0), sc1 = __expf(m1 - nm1);
        m0 = nm0; m1 = nm1;
        float su0 = 0.f, su1 = 0.f;
        #pragma unroll
        for (int nt = 0; nt < 8; nt++) {
            s[nt][0] = __expf(s[nt][0] - m0); su0 += s[nt][0];
            s[nt][1] = __expf(s[nt][1] - m0); su0 += s[nt][1];
            s[nt][2] = __expf(s[nt][2] - m1); su1 += s[nt][2];
            s[nt][3] = __expf(s[nt][3] - m1); su1 += s[nt][3];
        }
        su0 += __shfl_xor_sync(0xffffffffu, su0, 1);
        su0 += __shfl_xor_sync(0xffffffffu, su0, 2);
        su1 += __shfl_xor_sync(0xffffffffu, su1, 1);
        su1 += __shfl_xor_sync(0xffffffffu, su1, 2);
        l0 = l0 * sc0 + su0;
        l1 = l1 * sc1 + su1;
        #pragma unroll
        for (int nt = 0; nt < 8; nt++) {
            o[nt][0] *= sc0; o[nt][1] *= sc0;
            o[nt][2] *= sc1; o[nt][3] *= sc1;
        }

        // --- O += P @ V (3-pass split, ldmatrix.trans for V) ---
        #pragma unroll
        for (int kc = 0; kc < 4; kc++) {
            u32 pa[4], pl[4];
            pa[0] = pkbf(s[2*kc][0], s[2*kc][1]);
            pa[1] = pkbf(s[2*kc][2], s[2*kc][3]);
            pa[2] = pkbf(s[2*kc+1][0], s[2*kc+1][1]);
            pa[3] = pkbf(s[2*kc+1][2], s[2*kc+1][3]);
            pl[0] = pkbf_lo(s[2*kc][0], s[2*kc][1]);
            pl[1] = pkbf_lo(s[2*kc][2], s[2*kc][3]);
            pl[2] = pkbf_lo(s[2*kc+1][0], s[2*kc+1][1]);
            pl[3] = pkbf_lo(s[2*kc+1][2], s[2*kc+1][3]);
            u32 vh[4][4], vl[4][4];
            u32 kco = (u32)(kc * 16 * FST_) * 2;
            #pragma unroll
            for (int pr = 0; pr < 4; pr++) {
                ldsm4t(vh[pr][0], vh[pr][1], vh[pr][2], vh[pr][3], vbase + adV[pr] + kco);
                ldsm4t(vl[pr][0], vl[pr][1], vl[pr][2], vl[pr][3], vlbase + adV[pr] + kco);
            }
            #pragma unroll
            for (int nt = 0; nt < 8; nt++) {
                int pr = nt >> 1, of = (nt & 1) * 2;
                mma16816(o[nt], pa, vh[pr][of], vh[pr][of + 1]);
                mma16816(o[nt], pa, vl[pr][of], vl[pr][of + 1]);
                mma16816(o[nt], pl, vh[pr][of], vh[pr][of + 1]);
            }
        }
    }

    // --- epilogue: O /= l, write bf16 hi/lo (token-major, stride D_) ---
    float inv0 = 1.f / l0, inv1 = 1.f / l1;
    int r0 = b * S_ + q0 + wid * 16 + grp;
    size_t ob0 = (size_t)r0 * D_ + h * HD_ + tg * 2;
    size_t ob1 = (size_t)(r0 + 8) * D_ + h * HD_ + tg * 2;
    #pragma unroll
    for (int nt = 0; nt < 8; nt++) {
        float v00 = o[nt][0] * inv0, v01 = o[nt][1] * inv0;
        float v10 = o[nt][2] * inv1, v11 = o[nt][3] * inv1;
        *(__nv_bfloat162*)(g_Ahi + ob0 + nt * 8) = sp2hi(v00, v01);
        *(__nv_bfloat162*)(g_Alo + ob0 + nt * 8) = sp2lo(v00, v01);
        *(__nv_bfloat162*)(g_Ahi + ob1 + nt * 8) = sp2hi(v10, v11);
        *(__nv_bfloat162*)(g_Alo + ob1 + nt * 8) = sp2lo(v10, v11);
    }
}

// ---------------- router ------------------------------------------------------
__global__ __launch_bounds__(128) void router_kernel(const float* __restrict__ rw)
{
    int t = blockIdx.x * 4 + (threadIdx.x >> 5);
    int lane = threadIdx.x & 31;
    const float* x = g_X + (size_t)t * D_;
    float s = 0.f;
    for (int d = lane; d < D_; d += 32) s = fmaf(x[d], rw[d], s);
    #pragma unroll
    for (int o = 16; o > 0; o >>= 1) s += __shfl_xor_sync(0xffffffffu, s, o);
    if (lane == 0) g_P[t] = 1.f / (1.f + expf(-s));
}

// ---------------- exact stable top-k -> g_RS ----------------------------------
__global__ __launch_bounds__(256) void select_kernel()
{
    __shared__ float p[S_];
    int b = blockIdx.x;
    for (int t = threadIdx.x; t < S_; t += 256) p[t] = g_P[b * S_ + t];
    __syncthreads();
    int t = blockIdx.y * 256 + threadIdx.x;
    float pt = p[t];
    int rank = 0;
    for (int j = 0; j < S_; j++) {
        float pj = p[j];
        rank += (pj > pt) ? 1 : ((pj == pt && j < t) ? 1 : 0);
    }
    g_RS[b * S_ + t] = (rank < KSEL_) ? pt : 0.f;
}

// ---------------- driver ------------------------------------------------------
extern "C" void kernel_launch(void* const* d_in, const int* in_sizes, int n_in,
                              void* d_out, int out_size)
{
    const int*   ids          = (const int*)d_in[0];
    const int*   iter         = (const int*)d_in[1];
    const float* emb          = (const float*)d_in[2];
    const float* iemb         = (const float*)d_in[3];
    const float* attn_norm_w  = (const float*)d_in[4];
    const float* Wqkv         = (const float*)d_in[5];
    const float* wo_w         = (const float*)d_in[6];
    const float* router_w     = (const float*)d_in[7];
    const float* mlp_norm_w   = (const float*)d_in[8];
    const float* gate_w       = (const float*)d_in[9];
    const float* up_w         = (const float*)d_in[10];
    const float* down_w       = (const float*)d_in[11];
    const float* final_norm_w = (const float*)d_in[12];
    float* out = (float*)d_out;

    cudaFuncSetAttribute(mma_gemm_kernel,
                         cudaFuncAttributeMaxDynamicSharedMemorySize, SMEM_MM);

    embed_kernel<<<TOK_, 128>>>(ids, iter, emb, iemb);
    for (int l = 0; l < NL_; l++) {
        rmsnorm_kernel<<<TOK_, 128>>>(attn_norm_w + l * D_, nullptr);
        conv_w_kernel<<<QKVW_, 128>>>(Wqkv + (size_t)l * QKVW_ * D_, D_);
        mma_gemm_kernel<<<dim3(15, 128), 256, SMEM_MM>>>(QKVW_, D_, 10, 0, 0, 0);
        rope_kernel<<<TOK_, 160>>>();
        fa_kernel<<<dim3(S_ / 64, NH_, B_), 128>>>();
        conv_w_kernel<<<D_, 128>>>(wo_w + (size_t)l * D_ * D_, D_);
        mma_gemm_kernel<<<dim3(5, 128), 256, SMEM_MM>>>(D_, D_, 10, 1, 1, 0);
        router_kernel<<<TOK_ / 4, 128>>>(router_w + l * D_);
        select_kernel<<<dim3(B_, 8), 256>>>();
        rmsnorm_kernel<<<TOK_, 128>>>(mlp_norm_w + l * D_, nullptr);
        conv_w_kernel<<<FF_, 128>>>(gate_w + (size_t)l * FF_ * D_, D_);
        mma_gemm_kernel<<<dim3(14, 128), 256, SMEM_MM>>>(FF_, D_, 10, 0, 2, 0);
        conv_w_kernel<<<FF_, 128>>>(up_w + (size_t)l * FF_ * D_, D_);
        mma_gemm_kernel<<<dim3(14, 128), 256, SMEM_MM>>>(FF_, D_, 10, 3, 2, 0);
        conv_w_kernel<<<D_, 128>>>(down_w + (size_t)l * D_ * FF_, FF_);
        mma_gemm_kernel<<<dim3(5, 128), 256, SMEM_MM>>>(D_, FF_, 27, 2, 1, 1);
    }
    rmsnorm_kernel<<<TOK_, 128>>>(final_norm_w, out);
}

// round 14
// speedup vs baseline: 2.5636x; 1.5296x over previous
#include <cuda_runtime.h>
#include <cuda_bf16.h>
#include <math.h>

#define B_      8
#define S_      2048
#define D_      320
#define NH_     5
#define HD_     64
#define FF_     864
#define NL_     6
#define NLOOPS_ 8
#define TOK_    (B_*S_)          // 16384
#define KSEL_   1638             // int(2048*0.8)
#define QKVW_   (3*D_)           // 960

typedef unsigned int       u32;
typedef unsigned long long u64;

// ---------------- helpers -----------------------------------------------------
__device__ __forceinline__ u32 s2u(const void* p) {
    u32 a;
    asm("{ .reg .u64 t; cvta.to.shared.u64 t, %1; cvt.u32.u64 %0, t; }" : "=r"(a) : "l"(p));
    return a;
}
__device__ __forceinline__ void ldsm4(u32& r0, u32& r1, u32& r2, u32& r3, u32 addr) {
    asm volatile("ldmatrix.sync.aligned.m8n8.x4.shared.b16 {%0,%1,%2,%3},[%4];"
                 : "=r"(r0), "=r"(r1), "=r"(r2), "=r"(r3) : "r"(addr));
}
__device__ __forceinline__ void ldsm4t(u32& r0, u32& r1, u32& r2, u32& r3, u32 addr) {
    asm volatile("ldmatrix.sync.aligned.m8n8.x4.trans.shared.b16 {%0,%1,%2,%3},[%4];"
                 : "=r"(r0), "=r"(r1), "=r"(r2), "=r"(r3) : "r"(addr));
}
__device__ __forceinline__ void mma16816(float* c, const u32* a, u32 b0, u32 b1) {
    asm volatile(
        "mma.sync.aligned.m16n8k16.row.col.f32.bf16.bf16.f32 "
        "{%0,%1,%2,%3},{%4,%5,%6,%7},{%8,%9},{%0,%1,%2,%3};"
        : "+f"(c[0]), "+f"(c[1]), "+f"(c[2]), "+f"(c[3])
        : "r"(a[0]), "r"(a[1]), "r"(a[2]), "r"(a[3]), "r"(b0), "r"(b1));
}
__device__ __forceinline__ void cpa16(u32 s, const void* g, u32 src_bytes) {
    asm volatile("cp.async.cg.shared.global [%0],[%1],16,%2;"
                 :: "r"(s), "l"(g), "r"(src_bytes));
}
__device__ __forceinline__ void cpa_commit() { asm volatile("cp.async.commit_group;"); }
__device__ __forceinline__ void cpa_wait0()  { asm volatile("cp.async.wait_group 0;"); }
__device__ __forceinline__ void cpa_wait1()  { asm volatile("cp.async.wait_group 1;"); }

// ---------------- scratch (device globals) -----------------------------------
static __device__ float g_X[TOK_*D_];
static __device__ float g_QKV[TOK_*QKVW_];
static __device__ float g_T1[TOK_*FF_];
static __device__ float g_RS[TOK_];
static __device__ float g_P[TOK_];
static __device__ __nv_bfloat16 g_Ahi[(size_t)TOK_*D_];
static __device__ __nv_bfloat16 g_Alo[(size_t)TOK_*D_];
static __device__ __nv_bfloat16 g_Ghi[(size_t)TOK_*FF_];
static __device__ __nv_bfloat16 g_Glo[(size_t)TOK_*FF_];
static __device__ __nv_bfloat16 g_Qhi[(size_t)TOK_*D_];  // head-major [b,h,s,hd]
static __device__ __nv_bfloat16 g_Qlo[(size_t)TOK_*D_];
static __device__ __nv_bfloat16 g_Khi[(size_t)TOK_*D_];
static __device__ __nv_bfloat16 g_Klo[(size_t)TOK_*D_];
static __device__ __nv_bfloat16 g_Vhi[(size_t)TOK_*D_];
static __device__ __nv_bfloat16 g_Vlo[(size_t)TOK_*D_];
// per-type weight hi/lo (all layers)
static __device__ __nv_bfloat16 g_WqkvH[(size_t)NL_*QKVW_*D_], g_WqkvL[(size_t)NL_*QKVW_*D_];
static __device__ __nv_bfloat16 g_WwoH[(size_t)NL_*D_*D_],     g_WwoL[(size_t)NL_*D_*D_];
static __device__ __nv_bfloat16 g_WgtH[(size_t)NL_*FF_*D_],    g_WgtL[(size_t)NL_*FF_*D_];
static __device__ __nv_bfloat16 g_WupH[(size_t)NL_*FF_*D_],    g_WupL[(size_t)NL_*FF_*D_];
static __device__ __nv_bfloat16 g_WdnH[(size_t)NL_*D_*FF_],    g_WdnL[(size_t)NL_*D_*FF_];

__device__ __forceinline__ void split_store(__nv_bfloat16* hi, __nv_bfloat16* lo, float v) {
    __nv_bfloat16 h = __float2bfloat16(v);
    *hi = h;
    *lo = __float2bfloat16(v - __bfloat162float(h));
}
__device__ __forceinline__ __nv_bfloat162 sp2hi(float a, float b) {
    return __nv_bfloat162(__float2bfloat16(a), __float2bfloat16(b));
}
__device__ __forceinline__ __nv_bfloat162 sp2lo(float a, float b) {
    __nv_bfloat16 ha = __float2bfloat16(a), hb = __float2bfloat16(b);
    return __nv_bfloat162(__float2bfloat16(a - __bfloat162float(ha)),
                          __float2bfloat16(b - __bfloat162float(hb)));
}
__device__ __forceinline__ u32 pkbf(float a, float b) {
    __nv_bfloat162 v = sp2hi(a, b);
    return *(u32*)&v;
}
__device__ __forceinline__ u32 pkbf_lo(float a, float b) {
    __nv_bfloat162 v = sp2lo(a, b);
    return *(u32*)&v;
}

// ---------------- embedding ---------------------------------------------------
__global__ void embed_kernel(const int* __restrict__ ids, const int* __restrict__ iter,
                             const float* __restrict__ emb, const float* __restrict__ iemb)
{
    int t = blockIdx.x;
    int id = ids[t];
    int it = iter[0];
    const float* e = emb + (size_t)id * D_;
    const float* a = (it >= 0 && it < NLOOPS_) ? (iemb + (size_t)it * D_) : nullptr;
    for (int d = threadIdx.x; d < D_; d += blockDim.x) {
        float v = e[d];
        if (a) v += a[d];
        g_X[(size_t)t * D_ + d] = v;
    }
}

// ---------------- rmsnorm (fused bf16 hi/lo out) ------------------------------
__global__ __launch_bounds__(128) void rmsnorm_kernel(const float* __restrict__ w,
                                                      float* __restrict__ outp)
{
    int t = blockIdx.x;
    const float* x = g_X + (size_t)t * D_;
    float s = 0.f;
    for (int d = threadIdx.x; d < D_; d += 128) { float v = x[d]; s = fmaf(v, v, s); }
    #pragma unroll
    for (int o = 16; o > 0; o >>= 1) s += __shfl_xor_sync(0xffffffffu, s, o);
    __shared__ float red[4];
    if ((threadIdx.x & 31) == 0) red[threadIdx.x >> 5] = s;
    __syncthreads();
    s = red[0] + red[1] + red[2] + red[3];
    float inv = rsqrtf(s * (1.f / D_) + 1e-6f);
    if (outp) {
        float* dst = outp + (size_t)t * D_;
        for (int d = threadIdx.x; d < D_; d += 128) dst[d] = w[d] * x[d] * inv;
    } else {
        __nv_bfloat16* hi = g_Ahi + (size_t)t * D_;
        __nv_bfloat16* lo = g_Alo + (size_t)t * D_;
        for (int d = threadIdx.x; d < D_; d += 128)
            split_store(hi + d, lo + d, w[d] * x[d] * inv);
    }
}

// ------ weights fp32 -> bf16 hi/lo (all layers of one type per launch) --------
__global__ __launch_bounds__(128) void conv_w_kernel(const float* __restrict__ W,
                                                     int K, int wsel)
{
    size_t r = blockIdx.x;
    const float* s = W + r * K;
    __nv_bfloat16 *hi, *lo;
    if (wsel == 0)      { hi = g_WqkvH + r * K; lo = g_WqkvL + r * K; }
    else if (wsel == 1) { hi = g_WwoH  + r * K; lo = g_WwoL  + r * K; }
    else if (wsel == 2) { hi = g_WgtH  + r * K; lo = g_WgtL  + r * K; }
    else if (wsel == 3) { hi = g_WupH  + r * K; lo = g_WupL  + r * K; }
    else                { hi = g_WdnH  + r * K; lo = g_WdnL  + r * K; }
    for (int d = threadIdx.x; d < K; d += 128)
        split_store(hi + d, lo + d, s[d]);
}

// ====== HMMA bf16-split GEMM, cp.async 2-stage pipeline ======================
#define AST_    40
#define AH_SZ   (128*AST_*2)
#define BH_SZ   (64*AST_*2)
#define BUF_SZ  (2*AH_SZ + 2*BH_SZ)
#define SMEM_MM (2*BUF_SZ)

__global__ __launch_bounds__(256, 2) void mma_gemm_kernel(int N, int Kp, int nch,
                                                          int mode, int csel, int asel,
                                                          int wsel, int layer)
{
    extern __shared__ char dsm[];
    u32 sb = s2u(dsm);
    int tid = threadIdx.x, lane = tid & 31, wid = tid >> 5;
    int n0 = blockIdx.x * 64, m0 = blockIdx.y * 128;
    int mbase = (wid >> 1) * 32;
    int nbase = (wid & 1) * 32;

    const __nv_bfloat16* Ahi = asel ? g_Ghi : g_Ahi;
    const __nv_bfloat16* Alo = asel ? g_Glo : g_Alo;
    const __nv_bfloat16 *WH, *WL;
    if (wsel == 0)      { WH = g_WqkvH; WL = g_WqkvL; }
    else if (wsel == 1) { WH = g_WwoH;  WL = g_WwoL;  }
    else if (wsel == 2) { WH = g_WgtH;  WL = g_WgtL;  }
    else if (wsel == 3) { WH = g_WupH;  WL = g_WupL;  }
    else                { WH = g_WdnH;  WL = g_WdnL;  }
    size_t wbase = (size_t)layer * N * Kp;

    int arow0 = tid >> 2, asec = tid & 3;
    int brow = tid >> 2, bsec = tid & 3;
    u32 a_sof = (u32)(arow0 * AST_ + asec * 8) * 2;
    u32 b_sof = (u32)(brow * AST_ + bsec * 8) * 2;
    bool bok = (n0 + brow) < N;
    size_t a_go0 = (size_t)(m0 + arow0) * Kp + asec * 8;
    size_t a_go1 = (size_t)(m0 + arow0 + 64) * Kp + asec * 8;
    size_t b_go  = wbase + (size_t)(bok ? (n0 + brow) : 0) * Kp + bsec * 8;
    u32 bbytes = bok ? 16u : 0u;

    u32 adA[2][2], adB[2][2];
    #pragma unroll
    for (int mt = 0; mt < 2; mt++)
        #pragma unroll
        for (int ks = 0; ks < 2; ks++)
            adA[mt][ks] = (u32)((mbase + mt * 16 + (lane & 15)) * AST_ +
                                ks * 16 + (lane >> 4) * 8) * 2;
    #pragma unroll
    for (int pr = 0; pr < 2; pr++)
        #pragma unroll
        for (int ks = 0; ks < 2; ks++) {
            int sel = lane >> 3;
            int nr = nbase + pr * 16 + (sel >> 1) * 8 + (lane & 7);
            int kc = ks * 16 + (sel & 1) * 8;
            adB[pr][ks] = (u32)(nr * AST_ + kc) * 2;
        }

    float acc[2][4][4];
    #pragma unroll
    for (int mt = 0; mt < 2; mt++)
        #pragma unroll
        for (int nt = 0; nt < 4; nt++)
            #pragma unroll
            for (int q = 0; q < 4; q++) acc[mt][nt][q] = 0.f;

    {
        u32 bb = sb;
        cpa16(bb + a_sof, Ahi + a_go0, 16);
        cpa16(bb + a_sof + (u32)(64 * AST_ * 2), Ahi + a_go1, 16);
        cpa16(bb + AH_SZ + a_sof, Alo + a_go0, 16);
        cpa16(bb + AH_SZ + a_sof + (u32)(64 * AST_ * 2), Alo + a_go1, 16);
        cpa16(bb + 2 * AH_SZ + b_sof, WH + b_go, bbytes);
        cpa16(bb + 2 * AH_SZ + BH_SZ + b_sof, WL + b_go, bbytes);
        cpa_commit();
    }

    for (int c = 0; c < nch; c++) {
        cpa_wait0();
        __syncthreads();
        if (c + 1 < nch) {
            int ko = (c + 1) * 32;
            u32 bb = sb + ((c + 1) & 1) * BUF_SZ;
            cpa16(bb + a_sof, Ahi + a_go0 + ko, 16);
            cpa16(bb + a_sof + (u32)(64 * AST_ * 2), Ahi + a_go1 + ko, 16);
            cpa16(bb + AH_SZ + a_sof, Alo + a_go0 + ko, 16);
            cpa16(bb + AH_SZ + a_sof + (u32)(64 * AST_ * 2), Alo + a_go1 + ko, 16);
            cpa16(bb + 2 * AH_SZ + b_sof, WH + b_go + ko, bbytes);
            cpa16(bb + 2 * AH_SZ + BH_SZ + b_sof, WL + b_go + ko, bbytes);
            cpa_commit();
        }
        u32 bb = sb + (c & 1) * BUF_SZ;
        u32 baA = bb, baAl = bb + AH_SZ;
        u32 baB = bb + 2 * AH_SZ, baBl = bb + 2 * AH_SZ + BH_SZ;
        #pragma unroll
        for (int ks = 0; ks < 2; ks++) {
            u32 ah[2][4], al[2][4], bh[2][4], bl[2][4];
            #pragma unroll
            for (int mt = 0; mt < 2; mt++) {
                ldsm4(ah[mt][0], ah[mt][1], ah[mt][2], ah[mt][3], baA + adA[mt][ks]);
                ldsm4(al[mt][0], al[mt][1], al[mt][2], al[mt][3], baAl + adA[mt][ks]);
            }
            #pragma unroll
            for (int pr = 0; pr < 2; pr++) {
                ldsm4(bh[pr][0], bh[pr][1], bh[pr][2], bh[pr][3], baB + adB[pr][ks]);
                ldsm4(bl[pr][0], bl[pr][1], bl[pr][2], bl[pr][3], baBl + adB[pr][ks]);
            }
            #pragma unroll
            for (int mt = 0; mt < 2; mt++)
                #pragma unroll
                for (int nt = 0; nt < 4; nt++) {
                    int pr = nt >> 1, of = (nt & 1) * 2;
                    mma16816(acc[mt][nt], ah[mt], bh[pr][of], bh[pr][of + 1]);
                    mma16816(acc[mt][nt], ah[mt], bl[pr][of], bl[pr][of + 1]);
                    mma16816(acc[mt][nt], al[mt], bh[pr][of], bh[pr][of + 1]);
                }
        }
        __syncthreads();
    }

    int grp = lane >> 2, tg = lane & 3;
    float* C = (csel == 0) ? g_QKV : (csel == 1) ? g_X : g_T1;
    #pragma unroll
    for (int mt = 0; mt < 2; mt++) {
        int r0 = m0 + mbase + mt * 16 + grp;
        int r1 = r0 + 8;
        float rs0 = 1.f, rs1 = 1.f;
        if (mode == 2) { rs0 = g_RS[r0]; rs1 = g_RS[r1]; }
        #pragma unroll
        for (int nt = 0; nt < 4; nt++) {
            int nc = n0 + nbase + nt * 8 + tg * 2;
            if (nc >= N) continue;
            float a0 = acc[mt][nt][0], a1 = acc[mt][nt][1];
            float a2 = acc[mt][nt][2], a3 = acc[mt][nt][3];
            if (mode == 3) {
                const float* t0 = g_T1 + (size_t)r0 * N + nc;
                const float* t1 = g_T1 + (size_t)r1 * N + nc;
                float2 g0 = *(const float2*)t0, g1 = *(const float2*)t1;
                float v00 = (g0.x / (1.f + __expf(-g0.x))) * a0;
                float v01 = (g0.y / (1.f + __expf(-g0.y))) * a1;
                float v10 = (g1.x / (1.f + __expf(-g1.x))) * a2;
                float v11 = (g1.y / (1.f + __expf(-g1.y))) * a3;
                *(__nv_bfloat162*)(g_Ghi + (size_t)r0 * N + nc) = sp2hi(v00, v01);
                *(__nv_bfloat162*)(g_Glo + (size_t)r0 * N + nc) = sp2lo(v00, v01);
                *(__nv_bfloat162*)(g_Ghi + (size_t)r1 * N + nc) = sp2hi(v10, v11);
                *(__nv_bfloat162*)(g_Glo + (size_t)r1 * N + nc) = sp2lo(v10, v11);
            } else {
                float* p0 = C + (size_t)r0 * N + nc;
                float* p1 = C + (size_t)r1 * N + nc;
                if (mode == 0) {
                    *(float2*)p0 = make_float2(a0, a1);
                    *(float2*)p1 = make_float2(a2, a3);
                } else {
                    float2 o0 = *(const float2*)p0, o1 = *(const float2*)p1;
                    *(float2*)p0 = make_float2(o0.x + rs0 * a0, o0.y + rs0 * a1);
                    *(float2*)p1 = make_float2(o1.x + rs1 * a2, o1.y + rs1 * a3);
                }
            }
        }
    }
}

// ------ RoPE + bf16 hi/lo conversion of Q(x0.125)/K/V, head-major layout -----
__global__ __launch_bounds__(160) void rope_kernel()
{
    int t = blockIdx.x;
    int b = t >> 11, s = t & (S_ - 1);
    int h = threadIdx.x >> 5;
    int i = threadIdx.x & 31;
    float freq = expf(-((float)(2 * i) / (float)HD_) * 9.210340371976184f);
    float ang = (float)s * freq;
    float sn, cs;
    sincosf(ang, &sn, &cs);
    const float* qb = g_QKV + (size_t)t * QKVW_ + h * HD_;
    const float* kb = qb + D_;
    const float* vb = qb + 2 * D_;
    size_t base = ((size_t)(b * NH_ + h) * S_ + s) * HD_;
    float q1 = qb[i], q2 = qb[i + 32];
    float qr1 = (q1 * cs - q2 * sn) * 0.125f;
    float qr2 = (q2 * cs + q1 * sn) * 0.125f;
    split_store(g_Qhi + base + i,      g_Qlo + base + i,      qr1);
    split_store(g_Qhi + base + i + 32, g_Qlo + base + i + 32, qr2);
    float k1 = kb[i], k2 = kb[i + 32];
    split_store(g_Khi + base + i,      g_Klo + base + i,      k1 * cs - k2 * sn);
    split_store(g_Khi + base + i + 32, g_Klo + base + i + 32, k2 * cs + k1 * sn);
    split_store(g_Vhi + base + i,      g_Vlo + base + i,      vb[i]);
    split_store(g_Vhi + base + i + 32, g_Vlo + base + i + 32, vb[i + 32]);
}

// ====== HMMA flash attention, double-buffered cp.async K/V ===================
#define FST_    72
#define KSZ_    (64*FST_*2)      // 9216 bytes per array
#define FBUF_   (4*KSZ_)         // 36864 per stage
#define SMEM_FA (2*FBUF_)        // 73728

__global__ __launch_bounds__(128) void fa_kernel()
{
    extern __shared__ char fsm[];
    u32 sb = s2u(fsm);
    int tid = threadIdx.x, lane = tid & 31, wid = tid >> 5;
    int qt = blockIdx.x, h = blockIdx.y, b = blockIdx.z;
    int grp = lane >> 2, tg = lane & 3;
    size_t hrows = (size_t)(b * NH_ + h) * S_;
    int q0 = qt * 64;

    // Q fragments (A layout), loaded once
    u32 qh[4][4], ql[4][4];
    {
        const __nv_bfloat16* Qg = g_Qhi + (hrows + q0 + wid * 16 + grp) * HD_;
        const __nv_bfloat16* Qg2 = g_Qlo + (hrows + q0 + wid * 16 + grp) * HD_;
        #pragma unroll
        for (int ks = 0; ks < 4; ks++) {
            int col = ks * 16 + tg * 2;
            qh[ks][0] = *(const u32*)(Qg + col);
            qh[ks][1] = *(const u32*)(Qg + 8 * HD_ + col);
            qh[ks][2] = *(const u32*)(Qg + col + 8);
            qh[ks][3] = *(const u32*)(Qg + 8 * HD_ + col + 8);
            ql[ks][0] = *(const u32*)(Qg2 + col);
            ql[ks][1] = *(const u32*)(Qg2 + 8 * HD_ + col);
            ql[ks][2] = *(const u32*)(Qg2 + col + 8);
            ql[ks][3] = *(const u32*)(Qg2 + 8 * HD_ + col + 8);
        }
    }

    int sel = lane >> 3, wrow = lane & 7;
    u32 adK[4], adV[4];
    #pragma unroll
    for (int pr = 0; pr < 4; pr++) {
        adK[pr] = (u32)((pr * 16 + (sel >> 1) * 8 + wrow) * FST_ + (sel & 1) * 8) * 2;
        adV[pr] = (u32)(((sel & 1) * 8 + wrow) * FST_ + pr * 16 + (sel >> 1) * 8) * 2;
    }

    int srow = tid >> 1;
    u32 soff = (u32)(srow * FST_) * 2 + (u32)(tid & 1) * 64;
    int gcol = (tid & 1) * 32;

    float o[8][4];
    #pragma unroll
    for (int nt = 0; nt < 8; nt++)
        #pragma unroll
        for (int q = 0; q < 4; q++) o[nt][q] = 0.f;
    float m0 = -1e30f, m1 = -1e30f, l0 = 0.f, l1 = 0.f;

    int nkt = qt + 1;
    // prologue: stage tile 0 into buffer 0
    {
        size_t gr = (hrows + srow) * HD_ + gcol;
        u32 bb = sb;
        #pragma unroll
        for (int j = 0; j < 4; j++) {
            cpa16(bb + soff + j * 16,            g_Khi + gr + j * 8, 16);
            cpa16(bb + KSZ_ + soff + j * 16,     g_Klo + gr + j * 8, 16);
            cpa16(bb + 2 * KSZ_ + soff + j * 16, g_Vhi + gr + j * 8, 16);
            cpa16(bb + 3 * KSZ_ + soff + j * 16, g_Vlo + gr + j * 8, 16);
        }
        cpa_commit();
    }

    for (int kt = 0; kt < nkt; kt++) {
        if (kt + 1 < nkt) {
            size_t gr = (hrows + (kt + 1) * 64 + srow) * HD_ + gcol;
            u32 bb = sb + ((kt + 1) & 1) * FBUF_;
            #pragma unroll
            for (int j = 0; j < 4; j++) {
                cpa16(bb + soff + j * 16,            g_Khi + gr + j * 8, 16);
                cpa16(bb + KSZ_ + soff + j * 16,     g_Klo + gr + j * 8, 16);
                cpa16(bb + 2 * KSZ_ + soff + j * 16, g_Vhi + gr + j * 8, 16);
                cpa16(bb + 3 * KSZ_ + soff + j * 16, g_Vlo + gr + j * 8, 16);
            }
            cpa_commit();
            cpa_wait1();
        } else {
            cpa_wait0();
        }
        __syncthreads();
        u32 bb = sb + (kt & 1) * FBUF_;
        u32 kbase = bb, klbase = bb + KSZ_, vbase = bb + 2 * KSZ_, vlbase = bb + 3 * KSZ_;

        // S = Q @ K^T (3-pass split)
        float s[8][4];
        #pragma unroll
        for (int nt = 0; nt < 8; nt++)
            #pragma unroll
            for (int q = 0; q < 4; q++) s[nt][q] = 0.f;
        #pragma unroll
        for (int ks = 0; ks < 4; ks++) {
            u32 bh[4][4], bl[4][4];
            #pragma unroll
            for (int pr = 0; pr < 4; pr++) {
                ldsm4(bh[pr][0], bh[pr][1], bh[pr][2], bh[pr][3], kbase + adK[pr] + ks * 32);
                ldsm4(bl[pr][0], bl[pr][1], bl[pr][2], bl[pr][3], klbase + adK[pr] + ks * 32);
            }
            #pragma unroll
            for (int nt = 0; nt < 8; nt++) {
                int pr = nt >> 1, of = (nt & 1) * 2;
                mma16816(s[nt], qh[ks], bh[pr][of], bh[pr][of + 1]);
                mma16816(s[nt], qh[ks], bl[pr][of], bl[pr][of + 1]);
                mma16816(s[nt], ql[ks], bh[pr][of], bh[pr][of + 1]);
            }
        }

        if (kt == qt) {
            int rlo = wid * 16 + grp, rhi = rlo + 8;
            #pragma unroll
            for (int nt = 0; nt < 8; nt++) {
                int c0 = nt * 8 + tg * 2, c1 = c0 + 1;
                if (c0 > rlo) s[nt][0] = -1e30f;
                if (c1 > rlo) s[nt][1] = -1e30f;
                if (c0 > rhi) s[nt][2] = -1e30f;
                if (c1 > rhi) s[nt][3] = -1e30f;
            }
        }

        float t0 = -1e30f, t1 = -1e30f;
        #pragma unroll
        for (int nt = 0; nt < 8; nt++) {
            t0 = fmaxf(t0, fmaxf(s[nt][0], s[nt][1]));
            t1 = fmaxf(t1, fmaxf(s[nt][2], s[nt][3]));
        }
        t0 = fmaxf(t0, __shfl_xor_sync(0xffffffffu, t0, 1));
        t0 = fmaxf(t0, __shfl_xor_sync(0xffffffffu, t0, 2));
        t1 = fmaxf(t1, __shfl_xor_sync(0xffffffffu, t1, 1));
        t1 = fmaxf(t1, __shfl_xor_sync(0xffffffffu, t1, 2));
        float nm0 = fmaxf(m0, t0), nm1 = fmaxf(m1, t1);
        float sc0 = __expf(m0 - nm0), sc1 = __expf(m1 - nm1);
        m0 = nm0; m1 = nm1;
        float su0 = 0.f, su1 = 0.f;
        #pragma unroll
        for (int nt = 0; nt < 8; nt++) {
            s[nt][0] = __expf(s[nt][0] - m0); su0 += s[nt][0];
            s[nt][1] = __expf(s[nt][1] - m0); su0 += s[nt][1];
            s[nt][2] = __expf(s[nt][2] - m1); su1 += s[nt][2];
            s[nt][3] = __expf(s[nt][3] - m1); su1 += s[nt][3];
        }
        su0 += __shfl_xor_sync(0xffffffffu, su0, 1);
        su0 += __shfl_xor_sync(0xffffffffu, su0, 2);
        su1 += __shfl_xor_sync(0xffffffffu, su1, 1);
        su1 += __shfl_xor_sync(0xffffffffu, su1, 2);
        l0 = l0 * sc0 + su0;
        l1 = l1 * sc1 + su1;
        #pragma unroll
        for (int nt = 0; nt < 8; nt++) {
            o[nt][0] *= sc0; o[nt][1] *= sc0;
            o[nt][2] *= sc1; o[nt][3] *= sc1;
        }

        // O += P @ V (3-pass split, ldmatrix.trans for V)
        #pragma unroll
        for (int kc = 0; kc < 4; kc++) {
            u32 pa[4], pl[4];
            pa[0] = pkbf(s[2*kc][0], s[2*kc][1]);
            pa[1] = pkbf(s[2*kc][2], s[2*kc][3]);
            pa[2] = pkbf(s[2*kc+1][0], s[2*kc+1][1]);
            pa[3] = pkbf(s[2*kc+1][2], s[2*kc+1][3]);
            pl[0] = pkbf_lo(s[2*kc][0], s[2*kc][1]);
            pl[1] = pkbf_lo(s[2*kc][2], s[2*kc][3]);
            pl[2] = pkbf_lo(s[2*kc+1][0], s[2*kc+1][1]);
            pl[3] = pkbf_lo(s[2*kc+1][2], s[2*kc+1][3]);
            u32 vh[4][4], vl[4][4];
            u32 kco = (u32)(kc * 16 * FST_) * 2;
            #pragma unroll
            for (int pr = 0; pr < 4; pr++) {
                ldsm4t(vh[pr][0], vh[pr][1], vh[pr][2], vh[pr][3], vbase + adV[pr] + kco);
                ldsm4t(vl[pr][0], vl[pr][1], vl[pr][2], vl[pr][3], vlbase + adV[pr] + kco);
            }
            #pragma unroll
            for (int nt = 0; nt < 8; nt++) {
                int pr = nt >> 1, of = (nt & 1) * 2;
                mma16816(o[nt], pa, vh[pr][of], vh[pr][of + 1]);
                mma16816(o[nt], pa, vl[pr][of], vl[pr][of + 1]);
                mma16816(o[nt], pl, vh[pr][of], vh[pr][of + 1]);
            }
        }
        __syncthreads();
    }

    float inv0 = 1.f / l0, inv1 = 1.f / l1;
    int r0 = b * S_ + q0 + wid * 16 + grp;
    size_t ob0 = (size_t)r0 * D_ + h * HD_ + tg * 2;
    size_t ob1 = (size_t)(r0 + 8) * D_ + h * HD_ + tg * 2;
    #pragma unroll
    for (int nt = 0; nt < 8; nt++) {
        float v00 = o[nt][0] * inv0, v01 = o[nt][1] * inv0;
        float v10 = o[nt][2] * inv1, v11 = o[nt][3] * inv1;
        *(__nv_bfloat162*)(g_Ahi + ob0 + nt * 8) = sp2hi(v00, v01);
        *(__nv_bfloat162*)(g_Alo + ob0 + nt * 8) = sp2lo(v00, v01);
        *(__nv_bfloat162*)(g_Ahi + ob1 + nt * 8) = sp2hi(v10, v11);
        *(__nv_bfloat162*)(g_Alo + ob1 + nt * 8) = sp2lo(v10, v11);
    }
}

// ---------------- router ------------------------------------------------------
__global__ __launch_bounds__(128) void router_kernel(const float* __restrict__ rw)
{
    int t = blockIdx.x * 4 + (threadIdx.x >> 5);
    int lane = threadIdx.x & 31;
    const float* x = g_X + (size_t)t * D_;
    float s = 0.f;
    for (int d = lane; d < D_; d += 32) s = fmaf(x[d], rw[d], s);
    #pragma unroll
    for (int o = 16; o > 0; o >>= 1) s += __shfl_xor_sync(0xffffffffu, s, o);
    if (lane == 0) g_P[t] = 1.f / (1.f + expf(-s));
}

// ---------------- exact stable top-k -> g_RS ----------------------------------
__global__ __launch_bounds__(256) void select_kernel()
{
    __shared__ float p[S_];
    int b = blockIdx.x;
    for (int t = threadIdx.x; t < S_; t += 256) p[t] = g_P[b * S_ + t];
    __syncthreads();
    int t = blockIdx.y * 256 + threadIdx.x;
    float pt = p[t];
    int rank = 0;
    for (int j = 0; j < S_; j++) {
        float pj = p[j];
        rank += (pj > pt) ? 1 : ((pj == pt && j < t) ? 1 : 0);
    }
    g_RS[b * S_ + t] = (rank < KSEL_) ? pt : 0.f;
}

// ---------------- driver ------------------------------------------------------
extern "C" void kernel_launch(void* const* d_in, const int* in_sizes, int n_in,
                              void* d_out, int out_size)
{
    const int*   ids          = (const int*)d_in[0];
    const int*   iter         = (const int*)d_in[1];
    const float* emb          = (const float*)d_in[2];
    const float* iemb         = (const float*)d_in[3];
    const float* attn_norm_w  = (const float*)d_in[4];
    const float* Wqkv         = (const float*)d_in[5];
    const float* wo_w         = (const float*)d_in[6];
    const float* router_w     = (const float*)d_in[7];
    const float* mlp_norm_w   = (const float*)d_in[8];
    const float* gate_w       = (const float*)d_in[9];
    const float* up_w         = (const float*)d_in[10];
    const float* down_w       = (const float*)d_in[11];
    const float* final_norm_w = (const float*)d_in[12];
    float* out = (float*)d_out;

    cudaFuncSetAttribute(mma_gemm_kernel,
                         cudaFuncAttributeMaxDynamicSharedMemorySize, SMEM_MM);
    cudaFuncSetAttribute(fa_kernel,
                         cudaFuncAttributeMaxDynamicSharedMemorySize, SMEM_FA);

    embed_kernel<<<TOK_, 128>>>(ids, iter, emb, iemb);                 // 0
    for (int l = 0; l < NL_; l++) {
        if (l == 0)
            conv_w_kernel<<<NL_ * QKVW_, 128>>>(Wqkv, D_, 0);          // 1
        rmsnorm_kernel<<<TOK_, 128>>>(attn_norm_w + l * D_, nullptr);  // 2
        mma_gemm_kernel<<<dim3(15, 128), 256, SMEM_MM>>>(QKVW_, D_, 10, 0, 0, 0, 0, l); // 3
        rope_kernel<<<TOK_, 160>>>();                                  // 4
        fa_kernel<<<dim3(S_ / 64, NH_, B_), 128, SMEM_FA>>>();         // 5 <- profiled
        if (l == 0)
            conv_w_kernel<<<NL_ * D_, 128>>>(wo_w, D_, 1);
        mma_gemm_kernel<<<dim3(5, 128), 256, SMEM_MM>>>(D_, D_, 10, 1, 1, 0, 1, l);
        router_kernel<<<TOK_ / 4, 128>>>(router_w + l * D_);
        select_kernel<<<dim3(B_, 8), 256>>>();
        rmsnorm_kernel<<<TOK_, 128>>>(mlp_norm_w + l * D_, nullptr);
        if (l == 0) {
            conv_w_kernel<<<NL_ * FF_, 128>>>(gate_w, D_, 2);
            conv_w_kernel<<<NL_ * FF_, 128>>>(up_w, D_, 3);
            conv_w_kernel<<<NL_ * D_, 128>>>(down_w, FF_, 4);
        }
        mma_gemm_kernel<<<dim3(14, 128), 256, SMEM_MM>>>(FF_, D_, 10, 0, 2, 0, 2, l);
        mma_gemm_kernel<<<dim3(14, 128), 256, SMEM_MM>>>(FF_, D_, 10, 3, 2, 0, 3, l);
        mma_gemm_kernel<<<dim3(5, 128), 256, SMEM_MM>>>(D_, FF_, 27, 2, 1, 1, 4, l);
    }
    rmsnorm_kernel<<<TOK_, 128>>>(final_norm_w, out);
}

// round 15
// speedup vs baseline: 2.5716x; 1.0031x over previous
#include <cuda_runtime.h>
#include <cuda_bf16.h>
#include <math.h>

#define B_      8
#define S_      2048
#define D_      320
#define NH_     5
#define HD_     64
#define FF_     864
#define NL_     6
#define NLOOPS_ 8
#define TOK_    (B_*S_)          // 16384
#define KSEL_   1638             // int(2048*0.8)
#define QKVW_   (3*D_)           // 960

typedef unsigned int       u32;
typedef unsigned long long u64;

// ---------------- helpers -----------------------------------------------------
__device__ __forceinline__ u32 s2u(const void* p) {
    u32 a;
    asm("{ .reg .u64 t; cvta.to.shared.u64 t, %1; cvt.u32.u64 %0, t; }" : "=r"(a) : "l"(p));
    return a;
}
__device__ __forceinline__ void ldsm4(u32& r0, u32& r1, u32& r2, u32& r3, u32 addr) {
    asm volatile("ldmatrix.sync.aligned.m8n8.x4.shared.b16 {%0,%1,%2,%3},[%4];"
                 : "=r"(r0), "=r"(r1), "=r"(r2), "=r"(r3) : "r"(addr));
}
__device__ __forceinline__ void ldsm4t(u32& r0, u32& r1, u32& r2, u32& r3, u32 addr) {
    asm volatile("ldmatrix.sync.aligned.m8n8.x4.trans.shared.b16 {%0,%1,%2,%3},[%4];"
                 : "=r"(r0), "=r"(r1), "=r"(r2), "=r"(r3) : "r"(addr));
}
__device__ __forceinline__ void mma16816(float* c, const u32* a, u32 b0, u32 b1) {
    asm volatile(
        "mma.sync.aligned.m16n8k16.row.col.f32.bf16.bf16.f32 "
        "{%0,%1,%2,%3},{%4,%5,%6,%7},{%8,%9},{%0,%1,%2,%3};"
        : "+f"(c[0]), "+f"(c[1]), "+f"(c[2]), "+f"(c[3])
        : "r"(a[0]), "r"(a[1]), "r"(a[2]), "r"(a[3]), "r"(b0), "r"(b1));
}
__device__ __forceinline__ void cpa16(u32 s, const void* g, u32 src_bytes) {
    asm volatile("cp.async.cg.shared.global [%0],[%1],16,%2;"
                 :: "r"(s), "l"(g), "r"(src_bytes));
}
__device__ __forceinline__ void cpa_commit() { asm volatile("cp.async.commit_group;"); }
__device__ __forceinline__ void cpa_wait0()  { asm volatile("cp.async.wait_group 0;"); }
__device__ __forceinline__ void cpa_wait1()  { asm volatile("cp.async.wait_group 1;"); }

// ---------------- scratch (device globals) -----------------------------------
static __device__ float g_X[TOK_*D_];
static __device__ float g_QKV[TOK_*QKVW_];
static __device__ float g_T1[TOK_*FF_];
static __device__ float g_RS[TOK_];
static __device__ float g_P[TOK_];
static __device__ float2 g_CS[S_*32];                    // rope cos/sin table
static __device__ __nv_bfloat16 g_Ahi[(size_t)TOK_*D_];
static __device__ __nv_bfloat16 g_Alo[(size_t)TOK_*D_];
static __device__ __nv_bfloat16 g_Ghi[(size_t)TOK_*FF_];
static __device__ __nv_bfloat16 g_Glo[(size_t)TOK_*FF_];
static __device__ __nv_bfloat16 g_Qhi[(size_t)TOK_*D_];  // head-major [b,h,s,hd]
static __device__ __nv_bfloat16 g_Qlo[(size_t)TOK_*D_];
static __device__ __nv_bfloat16 g_Khi[(size_t)TOK_*D_];
static __device__ __nv_bfloat16 g_Klo[(size_t)TOK_*D_];
static __device__ __nv_bfloat16 g_Vhi[(size_t)TOK_*D_];
static __device__ __nv_bfloat16 g_Vlo[(size_t)TOK_*D_];
// per-type weight hi/lo (all layers)
static __device__ __nv_bfloat16 g_WqkvH[(size_t)NL_*QKVW_*D_], g_WqkvL[(size_t)NL_*QKVW_*D_];
static __device__ __nv_bfloat16 g_WwoH[(size_t)NL_*D_*D_],     g_WwoL[(size_t)NL_*D_*D_];
static __device__ __nv_bfloat16 g_WgtH[(size_t)NL_*FF_*D_],    g_WgtL[(size_t)NL_*FF_*D_];
static __device__ __nv_bfloat16 g_WupH[(size_t)NL_*FF_*D_],    g_WupL[(size_t)NL_*FF_*D_];
static __device__ __nv_bfloat16 g_WdnH[(size_t)NL_*D_*FF_],    g_WdnL[(size_t)NL_*D_*FF_];

__device__ __forceinline__ void split_store(__nv_bfloat16* hi, __nv_bfloat16* lo, float v) {
    __nv_bfloat16 h = __float2bfloat16(v);
    *hi = h;
    *lo = __float2bfloat16(v - __bfloat162float(h));
}
__device__ __forceinline__ __nv_bfloat162 sp2hi(float a, float b) {
    return __nv_bfloat162(__float2bfloat16(a), __float2bfloat16(b));
}
__device__ __forceinline__ __nv_bfloat162 sp2lo(float a, float b) {
    __nv_bfloat16 ha = __float2bfloat16(a), hb = __float2bfloat16(b);
    return __nv_bfloat162(__float2bfloat16(a - __bfloat162float(ha)),
                          __float2bfloat16(b - __bfloat162float(hb)));
}
__device__ __forceinline__ u32 pkbf(float a, float b) {
    __nv_bfloat162 v = sp2hi(a, b);
    return *(u32*)&v;
}
__device__ __forceinline__ u32 pkbf_lo(float a, float b) {
    __nv_bfloat162 v = sp2lo(a, b);
    return *(u32*)&v;
}

// ---------------- embedding ---------------------------------------------------
__global__ void embed_kernel(const int* __restrict__ ids, const int* __restrict__ iter,
                             const float* __restrict__ emb, const float* __restrict__ iemb)
{
    int t = blockIdx.x;
    int id = ids[t];
    int it = iter[0];
    const float* e = emb + (size_t)id * D_;
    const float* a = (it >= 0 && it < NLOOPS_) ? (iemb + (size_t)it * D_) : nullptr;
    for (int d = threadIdx.x; d < D_; d += blockDim.x) {
        float v = e[d];
        if (a) v += a[d];
        g_X[(size_t)t * D_ + d] = v;
    }
}

// ---------------- rope cos/sin table -----------------------------------------
__global__ void cstab_kernel()
{
    int s = blockIdx.x, i = threadIdx.x;
    float freq = expf(-((float)(2 * i) / (float)HD_) * 9.210340371976184f);
    float sn, cs;
    sincosf((float)s * freq, &sn, &cs);
    g_CS[s * 32 + i] = make_float2(cs, sn);
}

// ------ rmsnorm (fused bf16 hi/lo out) + optional fused router ----------------
__global__ __launch_bounds__(128) void rmsnorm_kernel(const float* __restrict__ w,
                                                      float* __restrict__ outp,
                                                      const float* __restrict__ rw)
{
    int t = blockIdx.x;
    const float* x = g_X + (size_t)t * D_;
    float s = 0.f, rdot = 0.f;
    for (int d = threadIdx.x; d < D_; d += 128) {
        float v = x[d];
        s = fmaf(v, v, s);
        if (rw) rdot = fmaf(v, rw[d], rdot);
    }
    #pragma unroll
    for (int o = 16; o > 0; o >>= 1) {
        s += __shfl_xor_sync(0xffffffffu, s, o);
        if (rw) rdot += __shfl_xor_sync(0xffffffffu, rdot, o);
    }
    __shared__ float red[4], red2[4];
    if ((threadIdx.x & 31) == 0) {
        red[threadIdx.x >> 5] = s;
        if (rw) red2[threadIdx.x >> 5] = rdot;
    }
    __syncthreads();
    s = red[0] + red[1] + red[2] + red[3];
    float inv = rsqrtf(s * (1.f / D_) + 1e-6f);
    if (rw && threadIdx.x == 0) {
        float rd = red2[0] + red2[1] + red2[2] + red2[3];
        g_P[t] = 1.f / (1.f + expf(-rd));
    }
    if (outp) {
        float* dst = outp + (size_t)t * D_;
        for (int d = threadIdx.x; d < D_; d += 128) dst[d] = w[d] * x[d] * inv;
    } else {
        __nv_bfloat16* hi = g_Ahi + (size_t)t * D_;
        __nv_bfloat16* lo = g_Alo + (size_t)t * D_;
        for (int d = threadIdx.x; d < D_; d += 128)
            split_store(hi + d, lo + d, w[d] * x[d] * inv);
    }
}

// ------ weights fp32 -> bf16 hi/lo (all layers of one type per launch) --------
__global__ __launch_bounds__(128) void conv_w_kernel(const float* __restrict__ W,
                                                     int K, int wsel)
{
    size_t r = blockIdx.x;
    const float* s = W + r * K;
    __nv_bfloat16 *hi, *lo;
    if (wsel == 0)      { hi = g_WqkvH + r * K; lo = g_WqkvL + r * K; }
    else if (wsel == 1) { hi = g_WwoH  + r * K; lo = g_WwoL  + r * K; }
    else if (wsel == 2) { hi = g_WgtH  + r * K; lo = g_WgtL  + r * K; }
    else if (wsel == 3) { hi = g_WupH  + r * K; lo = g_WupL  + r * K; }
    else                { hi = g_WdnH  + r * K; lo = g_WdnL  + r * K; }
    for (int d = threadIdx.x; d < K; d += 128)
        split_store(hi + d, lo + d, s[d]);
}

// ====== HMMA bf16-split GEMM, cp.async 2-stage pipeline ======================
#define AST_    40
#define AH_SZ   (128*AST_*2)
#define BH_SZ   (64*AST_*2)
#define BUF_SZ  (2*AH_SZ + 2*BH_SZ)
#define SMEM_MM (2*BUF_SZ)

__global__ __launch_bounds__(256, 2) void mma_gemm_kernel(int N, int Kp, int nch,
                                                          int mode, int csel, int asel,
                                                          int wsel, int layer)
{
    extern __shared__ char dsm[];
    u32 sb = s2u(dsm);
    int tid = threadIdx.x, lane = tid & 31, wid = tid >> 5;
    int n0 = blockIdx.x * 64, m0 = blockIdx.y * 128;
    int mbase = (wid >> 1) * 32;
    int nbase = (wid & 1) * 32;

    const __nv_bfloat16* Ahi = asel ? g_Ghi : g_Ahi;
    const __nv_bfloat16* Alo = asel ? g_Glo : g_Alo;
    const __nv_bfloat16 *WH, *WL;
    if (wsel == 0)      { WH = g_WqkvH; WL = g_WqkvL; }
    else if (wsel == 1) { WH = g_WwoH;  WL = g_WwoL;  }
    else if (wsel == 2) { WH = g_WgtH;  WL = g_WgtL;  }
    else if (wsel == 3) { WH = g_WupH;  WL = g_WupL;  }
    else                { WH = g_WdnH;  WL = g_WdnL;  }
    size_t wbase = (size_t)layer * N * Kp;

    int arow0 = tid >> 2, asec = tid & 3;
    int brow = tid >> 2, bsec = tid & 3;
    u32 a_sof = (u32)(arow0 * AST_ + asec * 8) * 2;
    u32 b_sof = (u32)(brow * AST_ + bsec * 8) * 2;
    bool bok = (n0 + brow) < N;
    size_t a_go0 = (size_t)(m0 + arow0) * Kp + asec * 8;
    size_t a_go1 = (size_t)(m0 + arow0 + 64) * Kp + asec * 8;
    size_t b_go  = wbase + (size_t)(bok ? (n0 + brow) : 0) * Kp + bsec * 8;
    u32 bbytes = bok ? 16u : 0u;

    u32 adA[2][2], adB[2][2];
    #pragma unroll
    for (int mt = 0; mt < 2; mt++)
        #pragma unroll
        for (int ks = 0; ks < 2; ks++)
            adA[mt][ks] = (u32)((mbase + mt * 16 + (lane & 15)) * AST_ +
                                ks * 16 + (lane >> 4) * 8) * 2;
    #pragma unroll
    for (int pr = 0; pr < 2; pr++)
        #pragma unroll
        for (int ks = 0; ks < 2; ks++) {
            int sel = lane >> 3;
            int nr = nbase + pr * 16 + (sel >> 1) * 8 + (lane & 7);
            int kc = ks * 16 + (sel & 1) * 8;
            adB[pr][ks] = (u32)(nr * AST_ + kc) * 2;
        }

    float acc[2][4][4];
    #pragma unroll
    for (int mt = 0; mt < 2; mt++)
        #pragma unroll
        for (int nt = 0; nt < 4; nt++)
            #pragma unroll
            for (int q = 0; q < 4; q++) acc[mt][nt][q] = 0.f;

    {
        u32 bb = sb;
        cpa16(bb + a_sof, Ahi + a_go0, 16);
        cpa16(bb + a_sof + (u32)(64 * AST_ * 2), Ahi + a_go1, 16);
        cpa16(bb + AH_SZ + a_sof, Alo + a_go0, 16);
        cpa16(bb + AH_SZ + a_sof + (u32)(64 * AST_ * 2), Alo + a_go1, 16);
        cpa16(bb + 2 * AH_SZ + b_sof, WH + b_go, bbytes);
        cpa16(bb + 2 * AH_SZ + BH_SZ + b_sof, WL + b_go, bbytes);
        cpa_commit();
    }

    for (int c = 0; c < nch; c++) {
        cpa_wait0();
        __syncthreads();
        if (c + 1 < nch) {
            int ko = (c + 1) * 32;
            u32 bb = sb + ((c + 1) & 1) * BUF_SZ;
            cpa16(bb + a_sof, Ahi + a_go0 + ko, 16);
            cpa16(bb + a_sof + (u32)(64 * AST_ * 2), Ahi + a_go1 + ko, 16);
            cpa16(bb + AH_SZ + a_sof, Alo + a_go0 + ko, 16);
            cpa16(bb + AH_SZ + a_sof + (u32)(64 * AST_ * 2), Alo + a_go1 + ko, 16);
            cpa16(bb + 2 * AH_SZ + b_sof, WH + b_go + ko, bbytes);
            cpa16(bb + 2 * AH_SZ + BH_SZ + b_sof, WL + b_go + ko, bbytes);
            cpa_commit();
        }
        u32 bb = sb + (c & 1) * BUF_SZ;
        u32 baA = bb, baAl = bb + AH_SZ;
        u32 baB = bb + 2 * AH_SZ, baBl = bb + 2 * AH_SZ + BH_SZ;
        #pragma unroll
        for (int ks = 0; ks < 2; ks++) {
            u32 ah[2][4], al[2][4], bh[2][4], bl[2][4];
            #pragma unroll
            for (int mt = 0; mt < 2; mt++) {
                ldsm4(ah[mt][0], ah[mt][1], ah[mt][2], ah[mt][3], baA + adA[mt][ks]);
                ldsm4(al[mt][0], al[mt][1], al[mt][2], al[mt][3], baAl + adA[mt][ks]);
            }
            #pragma unroll
            for (int pr = 0; pr < 2; pr++) {
                ldsm4(bh[pr][0], bh[pr][1], bh[pr][2], bh[pr][3], baB + adB[pr][ks]);
                ldsm4(bl[pr][0], bl[pr][1], bl[pr][2], bl[pr][3], baBl + adB[pr][ks]);
            }
            #pragma unroll
            for (int mt = 0; mt < 2; mt++)
                #pragma unroll
                for (int nt = 0; nt < 4; nt++) {
                    int pr = nt >> 1, of = (nt & 1) * 2;
                    mma16816(acc[mt][nt], ah[mt], bh[pr][of], bh[pr][of + 1]);
                    mma16816(acc[mt][nt], ah[mt], bl[pr][of], bl[pr][of + 1]);
                    mma16816(acc[mt][nt], al[mt], bh[pr][of], bh[pr][of + 1]);
                }
        }
    }

    int grp = lane >> 2, tg = lane & 3;
    float* C = (csel == 0) ? g_QKV : (csel == 1) ? g_X : g_T1;
    #pragma unroll
    for (int mt = 0; mt < 2; mt++) {
        int r0 = m0 + mbase + mt * 16 + grp;
        int r1 = r0 + 8;
        float rs0 = 1.f, rs1 = 1.f;
        if (mode == 2) { rs0 = g_RS[r0]; rs1 = g_RS[r1]; }
        #pragma unroll
        for (int nt = 0; nt < 4; nt++) {
            int nc = n0 + nbase + nt * 8 + tg * 2;
            if (nc >= N) continue;
            float a0 = acc[mt][nt][0], a1 = acc[mt][nt][1];
            float a2 = acc[mt][nt][2], a3 = acc[mt][nt][3];
            if (mode == 3) {
                const float* t0 = g_T1 + (size_t)r0 * N + nc;
                const float* t1 = g_T1 + (size_t)r1 * N + nc;
                float2 g0 = *(const float2*)t0, g1 = *(const float2*)t1;
                float v00 = (g0.x / (1.f + __expf(-g0.x))) * a0;
                float v01 = (g0.y / (1.f + __expf(-g0.y))) * a1;
                float v10 = (g1.x / (1.f + __expf(-g1.x))) * a2;
                float v11 = (g1.y / (1.f + __expf(-g1.y))) * a3;
                *(__nv_bfloat162*)(g_Ghi + (size_t)r0 * N + nc) = sp2hi(v00, v01);
                *(__nv_bfloat162*)(g_Glo + (size_t)r0 * N + nc) = sp2lo(v00, v01);
                *(__nv_bfloat162*)(g_Ghi + (size_t)r1 * N + nc) = sp2hi(v10, v11);
                *(__nv_bfloat162*)(g_Glo + (size_t)r1 * N + nc) = sp2lo(v10, v11);
            } else {
                float* p0 = C + (size_t)r0 * N + nc;
                float* p1 = C + (size_t)r1 * N + nc;
                if (mode == 0) {
                    *(float2*)p0 = make_float2(a0, a1);
                    *(float2*)p1 = make_float2(a2, a3);
                } else {
                    float2 o0 = *(const float2*)p0, o1 = *(const float2*)p1;
                    *(float2*)p0 = make_float2(o0.x + rs0 * a0, o0.y + rs0 * a1);
                    *(float2*)p1 = make_float2(o1.x + rs1 * a2, o1.y + rs1 * a3);
                }
            }
        }
    }
}

// ------ RoPE (table) + bf16 hi/lo conversion of Q(x0.125)/K/V ----------------
__global__ __launch_bounds__(160) void rope_kernel()
{
    int t = blockIdx.x;
    int b = t >> 11, s = t & (S_ - 1);
    int h = threadIdx.x >> 5;
    int i = threadIdx.x & 31;
    float2 cssn = g_CS[s * 32 + i];
    float cs = cssn.x, sn = cssn.y;
    const float* qb = g_QKV + (size_t)t * QKVW_ + h * HD_;
    const float* kb = qb + D_;
    const float* vb = qb + 2 * D_;
    size_t base = ((size_t)(b * NH_ + h) * S_ + s) * HD_;
    float q1 = qb[i], q2 = qb[i + 32];
    float qr1 = (q1 * cs - q2 * sn) * 0.125f;
    float qr2 = (q2 * cs + q1 * sn) * 0.125f;
    split_store(g_Qhi + base + i,      g_Qlo + base + i,      qr1);
    split_store(g_Qhi + base + i + 32, g_Qlo + base + i + 32, qr2);
    float k1 = kb[i], k2 = kb[i + 32];
    split_store(g_Khi + base + i,      g_Klo + base + i,      k1 * cs - k2 * sn);
    split_store(g_Khi + base + i + 32, g_Klo + base + i + 32, k2 * cs + k1 * sn);
    split_store(g_Vhi + base + i,      g_Vlo + base + i,      vb[i]);
    split_store(g_Vhi + base + i + 32, g_Vlo + base + i + 32, vb[i + 32]);
}

// ====== HMMA flash attention, double-buffered cp.async K/V ===================
#define FST_    72
#define KSZ_    (64*FST_*2)
#define FBUF_   (4*KSZ_)
#define SMEM_FA (2*FBUF_)

__global__ __launch_bounds__(128) void fa_kernel()
{
    extern __shared__ char fsm[];
    u32 sb = s2u(fsm);
    int tid = threadIdx.x, lane = tid & 31, wid = tid >> 5;
    int qt = blockIdx.x, h = blockIdx.y, b = blockIdx.z;
    int grp = lane >> 2, tg = lane & 3;
    size_t hrows = (size_t)(b * NH_ + h) * S_;
    int q0 = qt * 64;

    u32 qh[4][4], ql[4][4];
    {
        const __nv_bfloat16* Qg = g_Qhi + (hrows + q0 + wid * 16 + grp) * HD_;
        const __nv_bfloat16* Qg2 = g_Qlo + (hrows + q0 + wid * 16 + grp) * HD_;
        #pragma unroll
        for (int ks = 0; ks < 4; ks++) {
            int col = ks * 16 + tg * 2;
            qh[ks][0] = *(const u32*)(Qg + col);
            qh[ks][1] = *(const u32*)(Qg + 8 * HD_ + col);
            qh[ks][2] = *(const u32*)(Qg + col + 8);
            qh[ks][3] = *(const u32*)(Qg + 8 * HD_ + col + 8);
            ql[ks][0] = *(const u32*)(Qg2 + col);
            ql[ks][1] = *(const u32*)(Qg2 + 8 * HD_ + col);
            ql[ks][2] = *(const u32*)(Qg2 + col + 8);
            ql[ks][3] = *(const u32*)(Qg2 + 8 * HD_ + col + 8);
        }
    }

    int sel = lane >> 3, wrow = lane & 7;
    u32 adK[4], adV[4];
    #pragma unroll
    for (int pr = 0; pr < 4; pr++) {
        adK[pr] = (u32)((pr * 16 + (sel >> 1) * 8 + wrow) * FST_ + (sel & 1) * 8) * 2;
        adV[pr] = (u32)(((sel & 1) * 8 + wrow) * FST_ + pr * 16 + (sel >> 1) * 8) * 2;
    }

    int srow = tid >> 1;
    u32 soff = (u32)(srow * FST_) * 2 + (u32)(tid & 1) * 64;
    int gcol = (tid & 1) * 32;

    float o[8][4];
    #pragma unroll
    for (int nt = 0; nt < 8; nt++)
        #pragma unroll
        for (int q = 0; q < 4; q++) o[nt][q] = 0.f;
    float m0 = -1e30f, m1 = -1e30f, l0 = 0.f, l1 = 0.f;

    int nkt = qt + 1;
    {
        size_t gr = (hrows + srow) * HD_ + gcol;
        u32 bb = sb;
        #pragma unroll
        for (int j = 0; j < 4; j++) {
            cpa16(bb + soff + j * 16,            g_Khi + gr + j * 8, 16);
            cpa16(bb + KSZ_ + soff + j * 16,     g_Klo + gr + j * 8, 16);
            cpa16(bb + 2 * KSZ_ + soff + j * 16, g_Vhi + gr + j * 8, 16);
            cpa16(bb + 3 * KSZ_ + soff + j * 16, g_Vlo + gr + j * 8, 16);
        }
        cpa_commit();
    }

    for (int kt = 0; kt < nkt; kt++) {
        if (kt + 1 < nkt) {
            size_t gr = (hrows + (kt + 1) * 64 + srow) * HD_ + gcol;
            u32 bb = sb + ((kt + 1) & 1) * FBUF_;
            #pragma unroll
            for (int j = 0; j < 4; j++) {
                cpa16(bb + soff + j * 16,            g_Khi + gr + j * 8, 16);
                cpa16(bb + KSZ_ + soff + j * 16,     g_Klo + gr + j * 8, 16);
                cpa16(bb + 2 * KSZ_ + soff + j * 16, g_Vhi + gr + j * 8, 16);
                cpa16(bb + 3 * KSZ_ + soff + j * 16, g_Vlo + gr + j * 8, 16);
            }
            cpa_commit();
            cpa_wait1();
        } else {
            cpa_wait0();
        }
        __syncthreads();
        u32 bb = sb + (kt & 1) * FBUF_;
        u32 kbase = bb, klbase = bb + KSZ_, vbase = bb + 2 * KSZ_, vlbase = bb + 3 * KSZ_;

        float s[8][4];
        #pragma unroll
        for (int nt = 0; nt < 8; nt++)
            #pragma unroll
            for (int q = 0; q < 4; q++) s[nt][q] = 0.f;
        #pragma unroll
        for (int ks = 0; ks < 4; ks++) {
            u32 bh[4][4], bl[4][4];
            #pragma unroll
            for (int pr = 0; pr < 4; pr++) {
                ldsm4(bh[pr][0], bh[pr][1], bh[pr][2], bh[pr][3], kbase + adK[pr] + ks * 32);
                ldsm4(bl[pr][0], bl[pr][1], bl[pr][2], bl[pr][3], klbase + adK[pr] + ks * 32);
            }
            #pragma unroll
            for (int nt = 0; nt < 8; nt++) {
                int pr = nt >> 1, of = (nt & 1) * 2;
                mma16816(s[nt], qh[ks], bh[pr][of], bh[pr][of + 1]);
                mma16816(s[nt], qh[ks], bl[pr][of], bl[pr][of + 1]);
                mma16816(s[nt], ql[ks], bh[pr][of], bh[pr][of + 1]);
            }
        }

        if (kt == qt) {
            int rlo = wid * 16 + grp, rhi = rlo + 8;
            #pragma unroll
            for (int nt = 0; nt < 8; nt++) {
                int c0 = nt * 8 + tg * 2, c1 = c0 + 1;
                if (c0 > rlo) s[nt][0] = -1e30f;
                if (c1 > rlo) s[nt][1] = -1e30f;
                if (c0 > rhi) s[nt][2] = -1e30f;
                if (c1 > rhi) s[nt][3] = -1e30f;
            }
        }

        float t0 = -1e30f, t1 = -1e30f;
        #pragma unroll
        for (int nt = 0; nt < 8; nt++) {
            t0 = fmaxf(t0, fmaxf(s[nt][0], s[nt][1]));
            t1 = fmaxf(t1, fmaxf(s[nt][2], s[nt][3]));
        }
        t0 = fmaxf(t0, __shfl_xor_sync(0xffffffffu, t0, 1));
        t0 = fmaxf(t0, __shfl_xor_sync(0xffffffffu, t0, 2));
        t1 = fmaxf(t1, __shfl_xor_sync(0xffffffffu, t1, 1));
        t1 = fmaxf(t1, __shfl_xor_sync(0xffffffffu, t1, 2));
        float nm0 = fmaxf(m0, t0), nm1 = fmaxf(m1, t1);
        float sc0 = __expf(m0 - nm0), sc1 = __expf(m1 - nm1);
        m0 = nm0; m1 = nm1;
        float su0 = 0.f, su1 = 0.f;
        #pragma unroll
        for (int nt = 0; nt < 8; nt++) {
            s[nt][0] = __expf(s[nt][0] - m0); su0 += s[nt][0];
            s[nt][1] = __expf(s[nt][1] - m0); su0 += s[nt][1];
            s[nt][2] = __expf(s[nt][2] - m1); su1 += s[nt][2];
            s[nt][3] = __expf(s[nt][3] - m1); su1 += s[nt][3];
        }
        su0 += __shfl_xor_sync(0xffffffffu, su0, 1);
        su0 += __shfl_xor_sync(0xffffffffu, su0, 2);
        su1 += __shfl_xor_sync(0xffffffffu, su1, 1);
        su1 += __shfl_xor_sync(0xffffffffu, su1, 2);
        l0 = l0 * sc0 + su0;
        l1 = l1 * sc1 + su1;
        #pragma unroll
        for (int nt = 0; nt < 8; nt++) {
            o[nt][0] *= sc0; o[nt][1] *= sc0;
            o[nt][2] *= sc1; o[nt][3] *= sc1;
        }

        #pragma unroll
        for (int kc = 0; kc < 4; kc++) {
            u32 pa[4], pl[4];
            pa[0] = pkbf(s[2*kc][0], s[2*kc][1]);
            pa[1] = pkbf(s[2*kc][2], s[2*kc][3]);
            pa[2] = pkbf(s[2*kc+1][0], s[2*kc+1][1]);
            pa[3] = pkbf(s[2*kc+1][2], s[2*kc+1][3]);
            pl[0] = pkbf_lo(s[2*kc][0], s[2*kc][1]);
            pl[1] = pkbf_lo(s[2*kc][2], s[2*kc][3]);
            pl[2] = pkbf_lo(s[2*kc+1][0], s[2*kc+1][1]);
            pl[3] = pkbf_lo(s[2*kc+1][2], s[2*kc+1][3]);
            u32 vh[4][4], vl[4][4];
            u32 kco = (u32)(kc * 16 * FST_) * 2;
            #pragma unroll
            for (int pr = 0; pr < 4; pr++) {
                ldsm4t(vh[pr][0], vh[pr][1], vh[pr][2], vh[pr][3], vbase + adV[pr] + kco);
                ldsm4t(vl[pr][0], vl[pr][1], vl[pr][2], vl[pr][3], vlbase + adV[pr] + kco);
            }
            #pragma unroll
            for (int nt = 0; nt < 8; nt++) {
                int pr = nt >> 1, of = (nt & 1) * 2;
                mma16816(o[nt], pa, vh[pr][of], vh[pr][of + 1]);
                mma16816(o[nt], pa, vl[pr][of], vl[pr][of + 1]);
                mma16816(o[nt], pl, vh[pr][of], vh[pr][of + 1]);
            }
        }
        __syncthreads();
    }

    float inv0 = 1.f / l0, inv1 = 1.f / l1;
    int r0 = b * S_ + q0 + wid * 16 + grp;
    size_t ob0 = (size_t)r0 * D_ + h * HD_ + tg * 2;
    size_t ob1 = (size_t)(r0 + 8) * D_ + h * HD_ + tg * 2;
    #pragma unroll
    for (int nt = 0; nt < 8; nt++) {
        float v00 = o[nt][0] * inv0, v01 = o[nt][1] * inv0;
        float v10 = o[nt][2] * inv1, v11 = o[nt][3] * inv1;
        *(__nv_bfloat162*)(g_Ahi + ob0 + nt * 8) = sp2hi(v00, v01);
        *(__nv_bfloat162*)(g_Alo + ob0 + nt * 8) = sp2lo(v00, v01);
        *(__nv_bfloat162*)(g_Ahi + ob1 + nt * 8) = sp2hi(v10, v11);
        *(__nv_bfloat162*)(g_Alo + ob1 + nt * 8) = sp2lo(v10, v11);
    }
}

// ---------------- exact stable top-k -> g_RS ----------------------------------
__global__ __launch_bounds__(256) void select_kernel()
{
    __shared__ float p[S_];
    int b = blockIdx.x;
    for (int t = threadIdx.x; t < S_; t += 256) p[t] = g_P[b * S_ + t];
    __syncthreads();
    int t = blockIdx.y * 256 + threadIdx.x;
    float pt = p[t];
    int rank = 0;
    for (int j = 0; j < S_; j++) {
        float pj = p[j];
        rank += (pj > pt) ? 1 : ((pj == pt && j < t) ? 1 : 0);
    }
    g_RS[b * S_ + t] = (rank < KSEL_) ? pt : 0.f;
}

// ---------------- driver ------------------------------------------------------
extern "C" void kernel_launch(void* const* d_in, const int* in_sizes, int n_in,
                              void* d_out, int out_size)
{
    const int*   ids          = (const int*)d_in[0];
    const int*   iter         = (const int*)d_in[1];
    const float* emb          = (const float*)d_in[2];
    const float* iemb         = (const float*)d_in[3];
    const float* attn_norm_w  = (const float*)d_in[4];
    const float* Wqkv         = (const float*)d_in[5];
    const float* wo_w         = (const float*)d_in[6];
    const float* router_w     = (const float*)d_in[7];
    const float* mlp_norm_w   = (const float*)d_in[8];
    const float* gate_w       = (const float*)d_in[9];
    const float* up_w         = (const float*)d_in[10];
    const float* down_w       = (const float*)d_in[11];
    const float* final_norm_w = (const float*)d_in[12];
    float* out = (float*)d_out;

    cudaFuncSetAttribute(mma_gemm_kernel,
                         cudaFuncAttributeMaxDynamicSharedMemorySize, SMEM_MM);
    cudaFuncSetAttribute(fa_kernel,
                         cudaFuncAttributeMaxDynamicSharedMemorySize, SMEM_FA);

    embed_kernel<<<TOK_, 128>>>(ids, iter, emb, iemb);
    cstab_kernel<<<S_, 32>>>();
    for (int l = 0; l < NL_; l++) {
        if (l == 0)
            conv_w_kernel<<<NL_ * QKVW_, 128>>>(Wqkv, D_, 0);
        rmsnorm_kernel<<<TOK_, 128>>>(attn_norm_w + l * D_, nullptr, nullptr);
        mma_gemm_kernel<<<dim3(15, 128), 256, SMEM_MM>>>(QKVW_, D_, 10, 0, 0, 0, 0, l);
        rope_kernel<<<TOK_, 160>>>();
        fa_kernel<<<dim3(S_ / 64, NH_, B_), 128, SMEM_FA>>>();
        if (l == 0)
            conv_w_kernel<<<NL_ * D_, 128>>>(wo_w, D_, 1);
        mma_gemm_kernel<<<dim3(5, 128), 256, SMEM_MM>>>(D_, D_, 10, 1, 1, 0, 1, l);
        rmsnorm_kernel<<<TOK_, 128>>>(mlp_norm_w + l * D_, nullptr, router_w + l * D_);
        select_kernel<<<dim3(B_, 8), 256>>>();
        if (l == 0) {
            conv_w_kernel<<<NL_ * FF_, 128>>>(gate_w, D_, 2);
            conv_w_kernel<<<NL_ * FF_, 128>>>(up_w, D_, 3);
            conv_w_kernel<<<NL_ * D_, 128>>>(down_w, FF_, 4);
        }
        mma_gemm_kernel<<<dim3(14, 128), 256, SMEM_MM>>>(FF_, D_, 10, 0, 2, 0, 2, l);
        mma_gemm_kernel<<<dim3(14, 128), 256, SMEM_MM>>>(FF_, D_, 10, 3, 2, 0, 3, l);
        mma_gemm_kernel<<<dim3(5, 128), 256, SMEM_MM>>>(D_, FF_, 27, 2, 1, 1, 4, l);
    }
    rmsnorm_kernel<<<TOK_, 128>>>(final_norm_w, out, nullptr);
}

// round 16
// speedup vs baseline: 2.6544x; 1.0322x over previous
#include <cuda_runtime.h>
#include <cuda_bf16.h>
#include <math.h>

#define B_      8
#define S_      2048
#define D_      320
#define NH_     5
#define HD_     64
#define FF_     864
#define NL_     6
#define NLOOPS_ 8
#define TOK_    (B_*S_)          // 16384
#define KSEL_   1638             // int(2048*0.8)
#define QKVW_   (3*D_)           // 960

typedef unsigned int       u32;
typedef unsigned long long u64;

// ---------------- helpers -----------------------------------------------------
__device__ __forceinline__ u32 s2u(const void* p) {
    u32 a;
    asm("{ .reg .u64 t; cvta.to.shared.u64 t, %1; cvt.u32.u64 %0, t; }" : "=r"(a) : "l"(p));
    return a;
}
__device__ __forceinline__ void ldsm4(u32& r0, u32& r1, u32& r2, u32& r3, u32 addr) {
    asm volatile("ldmatrix.sync.aligned.m8n8.x4.shared.b16 {%0,%1,%2,%3},[%4];"
                 : "=r"(r0), "=r"(r1), "=r"(r2), "=r"(r3) : "r"(addr));
}
__device__ __forceinline__ void ldsm4t(u32& r0, u32& r1, u32& r2, u32& r3, u32 addr) {
    asm volatile("ldmatrix.sync.aligned.m8n8.x4.trans.shared.b16 {%0,%1,%2,%3},[%4];"
                 : "=r"(r0), "=r"(r1), "=r"(r2), "=r"(r3) : "r"(addr));
}
__device__ __forceinline__ void mma16816(float* c, const u32* a, u32 b0, u32 b1) {
    asm volatile(
        "mma.sync.aligned.m16n8k16.row.col.f32.bf16.bf16.f32 "
        "{%0,%1,%2,%3},{%4,%5,%6,%7},{%8,%9},{%0,%1,%2,%3};"
        : "+f"(c[0]), "+f"(c[1]), "+f"(c[2]), "+f"(c[3])
        : "r"(a[0]), "r"(a[1]), "r"(a[2]), "r"(a[3]), "r"(b0), "r"(b1));
}
__device__ __forceinline__ void cpa16(u32 s, const void* g, u32 src_bytes) {
    asm volatile("cp.async.cg.shared.global [%0],[%1],16,%2;"
                 :: "r"(s), "l"(g), "r"(src_bytes));
}
__device__ __forceinline__ void cpa_commit() { asm volatile("cp.async.commit_group;"); }
__device__ __forceinline__ void cpa_wait0()  { asm volatile("cp.async.wait_group 0;"); }
__device__ __forceinline__ void cpa_wait1()  { asm volatile("cp.async.wait_group 1;"); }

// ---------------- scratch (device globals) -----------------------------------
static __device__ float g_X[TOK_*D_];
static __device__ float g_QKV[TOK_*QKVW_];
static __device__ float g_T1[TOK_*FF_];
static __device__ float g_RS[TOK_];
static __device__ float g_P[TOK_];
static __device__ float2 g_CS[S_*32];                    // rope cos/sin table
static __device__ __nv_bfloat16 g_Ahi[(size_t)TOK_*D_];
static __device__ __nv_bfloat16 g_Alo[(size_t)TOK_*D_];
static __device__ __nv_bfloat16 g_Ghi[(size_t)TOK_*FF_];
static __device__ __nv_bfloat16 g_Glo[(size_t)TOK_*FF_];
static __device__ __nv_bfloat16 g_Qhi[(size_t)TOK_*D_];  // head-major [b,h,s,hd]
static __device__ __nv_bfloat16 g_Qlo[(size_t)TOK_*D_];
static __device__ __nv_bfloat16 g_Khi[(size_t)TOK_*D_];
static __device__ __nv_bfloat16 g_Klo[(size_t)TOK_*D_];
static __device__ __nv_bfloat16 g_Vhi[(size_t)TOK_*D_];
static __device__ __nv_bfloat16 g_Vlo[(size_t)TOK_*D_];
// per-type weight hi/lo (all layers)
static __device__ __nv_bfloat16 g_WqkvH[(size_t)NL_*QKVW_*D_], g_WqkvL[(size_t)NL_*QKVW_*D_];
static __device__ __nv_bfloat16 g_WwoH[(size_t)NL_*D_*D_],     g_WwoL[(size_t)NL_*D_*D_];
static __device__ __nv_bfloat16 g_WgtH[(size_t)NL_*FF_*D_],    g_WgtL[(size_t)NL_*FF_*D_];
static __device__ __nv_bfloat16 g_WupH[(size_t)NL_*FF_*D_],    g_WupL[(size_t)NL_*FF_*D_];
static __device__ __nv_bfloat16 g_WdnH[(size_t)NL_*D_*FF_],    g_WdnL[(size_t)NL_*D_*FF_];

__device__ __forceinline__ void split_store(__nv_bfloat16* hi, __nv_bfloat16* lo, float v) {
    __nv_bfloat16 h = __float2bfloat16(v);
    *hi = h;
    *lo = __float2bfloat16(v - __bfloat162float(h));
}
__device__ __forceinline__ __nv_bfloat162 sp2hi(float a, float b) {
    return __nv_bfloat162(__float2bfloat16(a), __float2bfloat16(b));
}
__device__ __forceinline__ __nv_bfloat162 sp2lo(float a, float b) {
    __nv_bfloat16 ha = __float2bfloat16(a), hb = __float2bfloat16(b);
    return __nv_bfloat162(__float2bfloat16(a - __bfloat162float(ha)),
                          __float2bfloat16(b - __bfloat162float(hb)));
}
__device__ __forceinline__ u32 pkbf(float a, float b) {
    __nv_bfloat162 v = sp2hi(a, b);
    return *(u32*)&v;
}
__device__ __forceinline__ u32 pkbf_lo(float a, float b) {
    __nv_bfloat162 v = sp2lo(a, b);
    return *(u32*)&v;
}

// ---------------- embedding ---------------------------------------------------
__global__ void embed_kernel(const int* __restrict__ ids, const int* __restrict__ iter,
                             const float* __restrict__ emb, const float* __restrict__ iemb)
{
    int t = blockIdx.x;
    int id = ids[t];
    int it = iter[0];
    const float* e = emb + (size_t)id * D_;
    const float* a = (it >= 0 && it < NLOOPS_) ? (iemb + (size_t)it * D_) : nullptr;
    for (int d = threadIdx.x; d < D_; d += blockDim.x) {
        float v = e[d];
        if (a) v += a[d];
        g_X[(size_t)t * D_ + d] = v;
    }
}

// ---------------- rope cos/sin table -----------------------------------------
__global__ void cstab_kernel()
{
    int s = blockIdx.x, i = threadIdx.x;
    float freq = expf(-((float)(2 * i) / (float)HD_) * 9.210340371976184f);
    float sn, cs;
    sincosf((float)s * freq, &sn, &cs);
    g_CS[s * 32 + i] = make_float2(cs, sn);
}

// ------ rmsnorm (fused bf16 hi/lo out) + optional fused router ----------------
__global__ __launch_bounds__(128) void rmsnorm_kernel(const float* __restrict__ w,
                                                      float* __restrict__ outp,
                                                      const float* __restrict__ rw)
{
    int t = blockIdx.x;
    const float* x = g_X + (size_t)t * D_;
    float s = 0.f, rdot = 0.f;
    for (int d = threadIdx.x; d < D_; d += 128) {
        float v = x[d];
        s = fmaf(v, v, s);
        if (rw) rdot = fmaf(v, rw[d], rdot);
    }
    #pragma unroll
    for (int o = 16; o > 0; o >>= 1) {
        s += __shfl_xor_sync(0xffffffffu, s, o);
        if (rw) rdot += __shfl_xor_sync(0xffffffffu, rdot, o);
    }
    __shared__ float red[4], red2[4];
    if ((threadIdx.x & 31) == 0) {
        red[threadIdx.x >> 5] = s;
        if (rw) red2[threadIdx.x >> 5] = rdot;
    }
    __syncthreads();
    s = red[0] + red[1] + red[2] + red[3];
    float inv = rsqrtf(s * (1.f / D_) + 1e-6f);
    if (rw && threadIdx.x == 0) {
        float rd = red2[0] + red2[1] + red2[2] + red2[3];
        g_P[t] = 1.f / (1.f + expf(-rd));
    }
    if (outp) {
        float* dst = outp + (size_t)t * D_;
        for (int d = threadIdx.x; d < D_; d += 128) dst[d] = w[d] * x[d] * inv;
    } else {
        __nv_bfloat16* hi = g_Ahi + (size_t)t * D_;
        __nv_bfloat16* lo = g_Alo + (size_t)t * D_;
        for (int d = threadIdx.x; d < D_; d += 128)
            split_store(hi + d, lo + d, w[d] * x[d] * inv);
    }
}

// ------ weights fp32 -> bf16 hi/lo (all layers of one type per launch) --------
__global__ __launch_bounds__(128) void conv_w_kernel(const float* __restrict__ W,
                                                     int K, int wsel)
{
    size_t r = blockIdx.x;
    const float* s = W + r * K;
    __nv_bfloat16 *hi, *lo;
    if (wsel == 0)      { hi = g_WqkvH + r * K; lo = g_WqkvL + r * K; }
    else if (wsel == 1) { hi = g_WwoH  + r * K; lo = g_WwoL  + r * K; }
    else if (wsel == 2) { hi = g_WgtH  + r * K; lo = g_WgtL  + r * K; }
    else if (wsel == 3) { hi = g_WupH  + r * K; lo = g_WupL  + r * K; }
    else                { hi = g_WdnH  + r * K; lo = g_WdnL  + r * K; }
    for (int d = threadIdx.x; d < K; d += 128)
        split_store(hi + d, lo + d, s[d]);
}

// ====== HMMA bf16-split GEMM, cp.async 2-stage pipeline, 3 CTAs/SM ==========
#define AST_    40
#define AH_SZ   (128*AST_*2)
#define BH_SZ   (64*AST_*2)
#define BUF_SZ  (2*AH_SZ + 2*BH_SZ)
#define SMEM_MM (2*BUF_SZ)

__global__ __launch_bounds__(256, 3) void mma_gemm_kernel(int N, int Kp, int nch,
                                                          int mode, int csel, int asel,
                                                          int wsel, int layer)
{
    extern __shared__ char dsm[];
    u32 sb = s2u(dsm);
    int tid = threadIdx.x, lane = tid & 31, wid = tid >> 5;
    int n0 = blockIdx.x * 64, m0 = blockIdx.y * 128;
    int mbase = (wid >> 1) * 32;
    int nbase = (wid & 1) * 32;

    const __nv_bfloat16* Ahi = asel ? g_Ghi : g_Ahi;
    const __nv_bfloat16* Alo = asel ? g_Glo : g_Alo;
    const __nv_bfloat16 *WH, *WL;
    if (wsel == 0)      { WH = g_WqkvH; WL = g_WqkvL; }
    else if (wsel == 1) { WH = g_WwoH;  WL = g_WwoL;  }
    else if (wsel == 2) { WH = g_WgtH;  WL = g_WgtL;  }
    else if (wsel == 3) { WH = g_WupH;  WL = g_WupL;  }
    else                { WH = g_WdnH;  WL = g_WdnL;  }
    size_t wbase = (size_t)layer * N * Kp;

    int arow0 = tid >> 2, asec = tid & 3;
    int brow = tid >> 2, bsec = tid & 3;
    u32 a_sof = (u32)(arow0 * AST_ + asec * 8) * 2;
    u32 b_sof = (u32)(brow * AST_ + bsec * 8) * 2;
    bool bok = (n0 + brow) < N;
    size_t a_go0 = (size_t)(m0 + arow0) * Kp + asec * 8;
    size_t a_go1 = (size_t)(m0 + arow0 + 64) * Kp + asec * 8;
    size_t b_go  = wbase + (size_t)(bok ? (n0 + brow) : 0) * Kp + bsec * 8;
    u32 bbytes = bok ? 16u : 0u;

    u32 adA[2][2], adB[2][2];
    #pragma unroll
    for (int mt = 0; mt < 2; mt++)
        #pragma unroll
        for (int ks = 0; ks < 2; ks++)
            adA[mt][ks] = (u32)((mbase + mt * 16 + (lane & 15)) * AST_ +
                                ks * 16 + (lane >> 4) * 8) * 2;
    #pragma unroll
    for (int pr = 0; pr < 2; pr++)
        #pragma unroll
        for (int ks = 0; ks < 2; ks++) {
            int sel = lane >> 3;
            int nr = nbase + pr * 16 + (sel >> 1) * 8 + (lane & 7);
            int kc = ks * 16 + (sel & 1) * 8;
            adB[pr][ks] = (u32)(nr * AST_ + kc) * 2;
        }

    float acc[2][4][4];
    #pragma unroll
    for (int mt = 0; mt < 2; mt++)
        #pragma unroll
        for (int nt = 0; nt < 4; nt++)
            #pragma unroll
            for (int q = 0; q < 4; q++) acc[mt][nt][q] = 0.f;

    {
        u32 bb = sb;
        cpa16(bb + a_sof, Ahi + a_go0, 16);
        cpa16(bb + a_sof + (u32)(64 * AST_ * 2), Ahi + a_go1, 16);
        cpa16(bb + AH_SZ + a_sof, Alo + a_go0, 16);
        cpa16(bb + AH_SZ + a_sof + (u32)(64 * AST_ * 2), Alo + a_go1, 16);
        cpa16(bb + 2 * AH_SZ + b_sof, WH + b_go, bbytes);
        cpa16(bb + 2 * AH_SZ + BH_SZ + b_sof, WL + b_go, bbytes);
        cpa_commit();
    }

    for (int c = 0; c < nch; c++) {
        cpa_wait0();
        __syncthreads();
        if (c + 1 < nch) {
            int ko = (c + 1) * 32;
            u32 bb = sb + ((c + 1) & 1) * BUF_SZ;
            cpa16(bb + a_sof, Ahi + a_go0 + ko, 16);
            cpa16(bb + a_sof + (u32)(64 * AST_ * 2), Ahi + a_go1 + ko, 16);
            cpa16(bb + AH_SZ + a_sof, Alo + a_go0 + ko, 16);
            cpa16(bb + AH_SZ + a_sof + (u32)(64 * AST_ * 2), Alo + a_go1 + ko, 16);
            cpa16(bb + 2 * AH_SZ + b_sof, WH + b_go + ko, bbytes);
            cpa16(bb + 2 * AH_SZ + BH_SZ + b_sof, WL + b_go + ko, bbytes);
            cpa_commit();
        }
        u32 bb = sb + (c & 1) * BUF_SZ;
        u32 baA = bb, baAl = bb + AH_SZ;
        u32 baB = bb + 2 * AH_SZ, baBl = bb + 2 * AH_SZ + BH_SZ;
        #pragma unroll
        for (int ks = 0; ks < 2; ks++) {
            u32 ah[2][4], al[2][4], bh[2][4], bl[2][4];
            #pragma unroll
            for (int mt = 0; mt < 2; mt++) {
                ldsm4(ah[mt][0], ah[mt][1], ah[mt][2], ah[mt][3], baA + adA[mt][ks]);
                ldsm4(al[mt][0], al[mt][1], al[mt][2], al[mt][3], baAl + adA[mt][ks]);
            }
            #pragma unroll
            for (int pr = 0; pr < 2; pr++) {
                ldsm4(bh[pr][0], bh[pr][1], bh[pr][2], bh[pr][3], baB + adB[pr][ks]);
                ldsm4(bl[pr][0], bl[pr][1], bl[pr][2], bl[pr][3], baBl + adB[pr][ks]);
            }
            #pragma unroll
            for (int mt = 0; mt < 2; mt++)
                #pragma unroll
                for (int nt = 0; nt < 4; nt++) {
                    int pr = nt >> 1, of = (nt & 1) * 2;
                    mma16816(acc[mt][nt], ah[mt], bh[pr][of], bh[pr][of + 1]);
                    mma16816(acc[mt][nt], ah[mt], bl[pr][of], bl[pr][of + 1]);
                    mma16816(acc[mt][nt], al[mt], bh[pr][of], bh[pr][of + 1]);
                }
        }
    }

    int grp = lane >> 2, tg = lane & 3;
    float* C = (csel == 0) ? g_QKV : (csel == 1) ? g_X : g_T1;
    #pragma unroll
    for (int mt = 0; mt < 2; mt++) {
        int r0 = m0 + mbase + mt * 16 + grp;
        int r1 = r0 + 8;
        float rs0 = 1.f, rs1 = 1.f;
        if (mode == 2) { rs0 = g_RS[r0]; rs1 = g_RS[r1]; }
        #pragma unroll
        for (int nt = 0; nt < 4; nt++) {
            int nc = n0 + nbase + nt * 8 + tg * 2;
            if (nc >= N) continue;
            float a0 = acc[mt][nt][0], a1 = acc[mt][nt][1];
            float a2 = acc[mt][nt][2], a3 = acc[mt][nt][3];
            if (mode == 3) {
                const float* t0 = g_T1 + (size_t)r0 * N + nc;
                const float* t1 = g_T1 + (size_t)r1 * N + nc;
                float2 g0 = *(const float2*)t0, g1 = *(const float2*)t1;
                float v00 = (g0.x / (1.f + __expf(-g0.x))) * a0;
                float v01 = (g0.y / (1.f + __expf(-g0.y))) * a1;
                float v10 = (g1.x / (1.f + __expf(-g1.x))) * a2;
                float v11 = (g1.y / (1.f + __expf(-g1.y))) * a3;
                *(__nv_bfloat162*)(g_Ghi + (size_t)r0 * N + nc) = sp2hi(v00, v01);
                *(__nv_bfloat162*)(g_Glo + (size_t)r0 * N + nc) = sp2lo(v00, v01);
                *(__nv_bfloat162*)(g_Ghi + (size_t)r1 * N + nc) = sp2hi(v10, v11);
                *(__nv_bfloat162*)(g_Glo + (size_t)r1 * N + nc) = sp2lo(v10, v11);
            } else {
                float* p0 = C + (size_t)r0 * N + nc;
                float* p1 = C + (size_t)r1 * N + nc;
                if (mode == 0) {
                    *(float2*)p0 = make_float2(a0, a1);
                    *(float2*)p1 = make_float2(a2, a3);
                } else {
                    float2 o0 = *(const float2*)p0, o1 = *(const float2*)p1;
                    *(float2*)p0 = make_float2(o0.x + rs0 * a0, o0.y + rs0 * a1);
                    *(float2*)p1 = make_float2(o1.x + rs1 * a2, o1.y + rs1 * a3);
                }
            }
        }
    }
}

// ------ RoPE (table) + bf16 hi/lo conversion of Q(x0.125)/K/V ----------------
__global__ __launch_bounds__(160) void rope_kernel()
{
    int t = blockIdx.x;
    int b = t >> 11, s = t & (S_ - 1);
    int h = threadIdx.x >> 5;
    int i = threadIdx.x & 31;
    float2 cssn = g_CS[s * 32 + i];
    float cs = cssn.x, sn = cssn.y;
    const float* qb = g_QKV + (size_t)t * QKVW_ + h * HD_;
    const float* kb = qb + D_;
    const float* vb = qb + 2 * D_;
    size_t base = ((size_t)(b * NH_ + h) * S_ + s) * HD_;
    float q1 = qb[i], q2 = qb[i + 32];
    float qr1 = (q1 * cs - q2 * sn) * 0.125f;
    float qr2 = (q2 * cs + q1 * sn) * 0.125f;
    split_store(g_Qhi + base + i,      g_Qlo + base + i,      qr1);
    split_store(g_Qhi + base + i + 32, g_Qlo + base + i + 32, qr2);
    float k1 = kb[i], k2 = kb[i + 32];
    split_store(g_Khi + base + i,      g_Klo + base + i,      k1 * cs - k2 * sn);
    split_store(g_Khi + base + i + 32, g_Klo + base + i + 32, k2 * cs + k1 * sn);
    split_store(g_Vhi + base + i,      g_Vlo + base + i,      vb[i]);
    split_store(g_Vhi + base + i + 32, g_Vlo + base + i + 32, vb[i + 32]);
}

// ====== HMMA flash attention, double-buffered cp.async K/V ===================
#define FST_    72
#define KSZ_    (64*FST_*2)
#define FBUF_   (4*KSZ_)
#define SMEM_FA (2*FBUF_)

__global__ __launch_bounds__(128) void fa_kernel()
{
    extern __shared__ char fsm[];
    u32 sb = s2u(fsm);
    int tid = threadIdx.x, lane = tid & 31, wid = tid >> 5;
    int qt = blockIdx.x, h = blockIdx.y, b = blockIdx.z;
    int grp = lane >> 2, tg = lane & 3;
    size_t hrows = (size_t)(b * NH_ + h) * S_;
    int q0 = qt * 64;

    u32 qh[4][4], ql[4][4];
    {
        const __nv_bfloat16* Qg = g_Qhi + (hrows + q0 + wid * 16 + grp) * HD_;
        const __nv_bfloat16* Qg2 = g_Qlo + (hrows + q0 + wid * 16 + grp) * HD_;
        #pragma unroll
        for (int ks = 0; ks < 4; ks++) {
            int col = ks * 16 + tg * 2;
            qh[ks][0] = *(const u32*)(Qg + col);
            qh[ks][1] = *(const u32*)(Qg + 8 * HD_ + col);
            qh[ks][2] = *(const u32*)(Qg + col + 8);
            qh[ks][3] = *(const u32*)(Qg + 8 * HD_ + col + 8);
            ql[ks][0] = *(const u32*)(Qg2 + col);
            ql[ks][1] = *(const u32*)(Qg2 + 8 * HD_ + col);
            ql[ks][2] = *(const u32*)(Qg2 + col + 8);
            ql[ks][3] = *(const u32*)(Qg2 + 8 * HD_ + col + 8);
        }
    }

    int sel = lane >> 3, wrow = lane & 7;
    u32 adK[4], adV[4];
    #pragma unroll
    for (int pr = 0; pr < 4; pr++) {
        adK[pr] = (u32)((pr * 16 + (sel >> 1) * 8 + wrow) * FST_ + (sel & 1) * 8) * 2;
        adV[pr] = (u32)(((sel & 1) * 8 + wrow) * FST_ + pr * 16 + (sel >> 1) * 8) * 2;
    }

    int srow = tid >> 1;
    u32 soff = (u32)(srow * FST_) * 2 + (u32)(tid & 1) * 64;
    int gcol = (tid & 1) * 32;

    float o[8][4];
    #pragma unroll
    for (int nt = 0; nt < 8; nt++)
        #pragma unroll
        for (int q = 0; q < 4; q++) o[nt][q] = 0.f;
    float m0 = -1e30f, m1 = -1e30f, l0 = 0.f, l1 = 0.f;

    int nkt = qt + 1;
    {
        size_t gr = (hrows + srow) * HD_ + gcol;
        u32 bb = sb;
        #pragma unroll
        for (int j = 0; j < 4; j++) {
            cpa16(bb + soff + j * 16,            g_Khi + gr + j * 8, 16);
            cpa16(bb + KSZ_ + soff + j * 16,     g_Klo + gr + j * 8, 16);
            cpa16(bb + 2 * KSZ_ + soff + j * 16, g_Vhi + gr + j * 8, 16);
            cpa16(bb + 3 * KSZ_ + soff + j * 16, g_Vlo + gr + j * 8, 16);
        }
        cpa_commit();
    }

    for (int kt = 0; kt < nkt; kt++) {
        if (kt + 1 < nkt) {
            size_t gr = (hrows + (kt + 1) * 64 + srow) * HD_ + gcol;
            u32 bb = sb + ((kt + 1) & 1) * FBUF_;
            #pragma unroll
            for (int j = 0; j < 4; j++) {
                cpa16(bb + soff + j * 16,            g_Khi + gr + j * 8, 16);
                cpa16(bb + KSZ_ + soff + j * 16,     g_Klo + gr + j * 8, 16);
                cpa16(bb + 2 * KSZ_ + soff + j * 16, g_Vhi + gr + j * 8, 16);
                cpa16(bb + 3 * KSZ_ + soff + j * 16, g_Vlo + gr + j * 8, 16);
            }
            cpa_commit();
            cpa_wait1();
        } else {
            cpa_wait0();
        }
        __syncthreads();
        u32 bb = sb + (kt & 1) * FBUF_;
        u32 kbase = bb, klbase = bb + KSZ_, vbase = bb + 2 * KSZ_, vlbase = bb + 3 * KSZ_;

        float s[8][4];
        #pragma unroll
        for (int nt = 0; nt < 8; nt++)
            #pragma unroll
            for (int q = 0; q < 4; q++) s[nt][q] = 0.f;
        #pragma unroll
        for (int ks = 0; ks < 4; ks++) {
            u32 bh[4][4], bl[4][4];
            #pragma unroll
            for (int pr = 0; pr < 4; pr++) {
                ldsm4(bh[pr][0], bh[pr][1], bh[pr][2], bh[pr][3], kbase + adK[pr] + ks * 32);
                ldsm4(bl[pr][0], bl[pr][1], bl[pr][2], bl[pr][3], klbase + adK[pr] + ks * 32);
            }
            #pragma unroll
            for (int nt = 0; nt < 8; nt++) {
                int pr = nt >> 1, of = (nt & 1) * 2;
                mma16816(s[nt], qh[ks], bh[pr][of], bh[pr][of + 1]);
                mma16816(s[nt], qh[ks], bl[pr][of], bl[pr][of + 1]);
                mma16816(s[nt], ql[ks], bh[pr][of], bh[pr][of + 1]);
            }
        }

        if (kt == qt) {
            int rlo = wid * 16 + grp, rhi = rlo + 8;
            #pragma unroll
            for (int nt = 0; nt < 8; nt++) {
                int c0 = nt * 8 + tg * 2, c1 = c0 + 1;
                if (c0 > rlo) s[nt][0] = -1e30f;
                if (c1 > rlo) s[nt][1] = -1e30f;
                if (c0 > rhi) s[nt][2] = -1e30f;
                if (c1 > rhi) s[nt][3] = -1e30f;
            }
        }

        float t0 = -1e30f, t1 = -1e30f;
        #pragma unroll
        for (int nt = 0; nt < 8; nt++) {
            t0 = fmaxf(t0, fmaxf(s[nt][0], s[nt][1]));
            t1 = fmaxf(t1, fmaxf(s[nt][2], s[nt][3]));
        }
        t0 = fmaxf(t0, __shfl_xor_sync(0xffffffffu, t0, 1));
        t0 = fmaxf(t0, __shfl_xor_sync(0xffffffffu, t0, 2));
        t1 = fmaxf(t1, __shfl_xor_sync(0xffffffffu, t1, 1));
        t1 = fmaxf(t1, __shfl_xor_sync(0xffffffffu, t1, 2));
        float nm0 = fmaxf(m0, t0), nm1 = fmaxf(m1, t1);
        float sc0 = __expf(m0 - nm0), sc1 = __expf(m1 - nm1);
        m0 = nm0; m1 = nm1;
        float su0 = 0.f, su1 = 0.f;
        #pragma unroll
        for (int nt = 0; nt < 8; nt++) {
            s[nt][0] = __expf(s[nt][0] - m0); su0 += s[nt][0];
            s[nt][1] = __expf(s[nt][1] - m0); su0 += s[nt][1];
            s[nt][2] = __expf(s[nt][2] - m1); su1 += s[nt][2];
            s[nt][3] = __expf(s[nt][3] - m1); su1 += s[nt][3];
        }
        su0 += __shfl_xor_sync(0xffffffffu, su0, 1);
        su0 += __shfl_xor_sync(0xffffffffu, su0, 2);
        su1 += __shfl_xor_sync(0xffffffffu, su1, 1);
        su1 += __shfl_xor_sync(0xffffffffu, su1, 2);
        l0 = l0 * sc0 + su0;
        l1 = l1 * sc1 + su1;
        #pragma unroll
        for (int nt = 0; nt < 8; nt++) {
            o[nt][0] *= sc0; o[nt][1] *= sc0;
            o[nt][2] *= sc1; o[nt][3] *= sc1;
        }

        #pragma unroll
        for (int kc = 0; kc < 4; kc++) {
            u32 pa[4], pl[4];
            pa[0] = pkbf(s[2*kc][0], s[2*kc][1]);
            pa[1] = pkbf(s[2*kc][2], s[2*kc][3]);
            pa[2] = pkbf(s[2*kc+1][0], s[2*kc+1][1]);
            pa[3] = pkbf(s[2*kc+1][2], s[2*kc+1][3]);
            pl[0] = pkbf_lo(s[2*kc][0], s[2*kc][1]);
            pl[1] = pkbf_lo(s[2*kc][2], s[2*kc][3]);
            pl[2] = pkbf_lo(s[2*kc+1][0], s[2*kc+1][1]);
            pl[3] = pkbf_lo(s[2*kc+1][2], s[2*kc+1][3]);
            u32 vh[4][4], vl[4][4];
            u32 kco = (u32)(kc * 16 * FST_) * 2;
            #pragma unroll
            for (int pr = 0; pr < 4; pr++) {
                ldsm4t(vh[pr][0], vh[pr][1], vh[pr][2], vh[pr][3], vbase + adV[pr] + kco);
                ldsm4t(vl[pr][0], vl[pr][1], vl[pr][2], vl[pr][3], vlbase + adV[pr] + kco);
            }
            #pragma unroll
            for (int nt = 0; nt < 8; nt++) {
                int pr = nt >> 1, of = (nt & 1) * 2;
                mma16816(o[nt], pa, vh[pr][of], vh[pr][of + 1]);
                mma16816(o[nt], pa, vl[pr][of], vl[pr][of + 1]);
                mma16816(o[nt], pl, vh[pr][of], vh[pr][of + 1]);
            }
        }
        __syncthreads();
    }

    float inv0 = 1.f / l0, inv1 = 1.f / l1;
    int r0 = b * S_ + q0 + wid * 16 + grp;
    size_t ob0 = (size_t)r0 * D_ + h * HD_ + tg * 2;
    size_t ob1 = (size_t)(r0 + 8) * D_ + h * HD_ + tg * 2;
    #pragma unroll
    for (int nt = 0; nt < 8; nt++) {
        float v00 = o[nt][0] * inv0, v01 = o[nt][1] * inv0;
        float v10 = o[nt][2] * inv1, v11 = o[nt][3] * inv1;
        *(__nv_bfloat162*)(g_Ahi + ob0 + nt * 8) = sp2hi(v00, v01);
        *(__nv_bfloat162*)(g_Alo + ob0 + nt * 8) = sp2lo(v00, v01);
        *(__nv_bfloat162*)(g_Ahi + ob1 + nt * 8) = sp2hi(v10, v11);
        *(__nv_bfloat162*)(g_Alo + ob1 + nt * 8) = sp2lo(v10, v11);
    }
}

// ---------------- exact stable top-k -> g_RS ----------------------------------
__global__ __launch_bounds__(256) void select_kernel()
{
    __shared__ float p[S_];
    int b = blockIdx.x;
    for (int t = threadIdx.x; t < S_; t += 256) p[t] = g_P[b * S_ + t];
    __syncthreads();
    int t = blockIdx.y * 256 + threadIdx.x;
    float pt = p[t];
    int rank = 0;
    for (int j = 0; j < S_; j++) {
        float pj = p[j];
        rank += (pj > pt) ? 1 : ((pj == pt && j < t) ? 1 : 0);
    }
    g_RS[b * S_ + t] = (rank < KSEL_) ? pt : 0.f;
}

// ---------------- driver ------------------------------------------------------
extern "C" void kernel_launch(void* const* d_in, const int* in_sizes, int n_in,
                              void* d_out, int out_size)
{
    const int*   ids          = (const int*)d_in[0];
    const int*   iter         = (const int*)d_in[1];
    const float* emb          = (const float*)d_in[2];
    const float* iemb         = (const float*)d_in[3];
    const float* attn_norm_w  = (const float*)d_in[4];
    const float* Wqkv         = (const float*)d_in[5];
    const float* wo_w         = (const float*)d_in[6];
    const float* router_w     = (const float*)d_in[7];
    const float* mlp_norm_w   = (const float*)d_in[8];
    const float* gate_w       = (const float*)d_in[9];
    const float* up_w         = (const float*)d_in[10];
    const float* down_w       = (const float*)d_in[11];
    const float* final_norm_w = (const float*)d_in[12];
    float* out = (float*)d_out;

    cudaFuncSetAttribute(mma_gemm_kernel,
                         cudaFuncAttributeMaxDynamicSharedMemorySize, SMEM_MM);
    cudaFuncSetAttribute(fa_kernel,
                         cudaFuncAttributeMaxDynamicSharedMemorySize, SMEM_FA);

    embed_kernel<<<TOK_, 128>>>(ids, iter, emb, iemb);
    cstab_kernel<<<S_, 32>>>();
    for (int l = 0; l < NL_; l++) {
        if (l == 0)
            conv_w_kernel<<<NL_ * QKVW_, 128>>>(Wqkv, D_, 0);
        rmsnorm_kernel<<<TOK_, 128>>>(attn_norm_w + l * D_, nullptr, nullptr);
        mma_gemm_kernel<<<dim3(15, 128), 256, SMEM_MM>>>(QKVW_, D_, 10, 0, 0, 0, 0, l);
        rope_kernel<<<TOK_, 160>>>();
        fa_kernel<<<dim3(S_ / 64, NH_, B_), 128, SMEM_FA>>>();
        if (l == 0)
            conv_w_kernel<<<NL_ * D_, 128>>>(wo_w, D_, 1);
        mma_gemm_kernel<<<dim3(5, 128), 256, SMEM_MM>>>(D_, D_, 10, 1, 1, 0, 1, l);
        rmsnorm_kernel<<<TOK_, 128>>>(mlp_norm_w + l * D_, nullptr, router_w + l * D_);
        select_kernel<<<dim3(B_, 8), 256>>>();
        if (l == 0) {
            conv_w_kernel<<<NL_ * FF_, 128>>>(gate_w, D_, 2);
            conv_w_kernel<<<NL_ * FF_, 128>>>(up_w, D_, 3);
            conv_w_kernel<<<NL_ * D_, 128>>>(down_w, FF_, 4);
        }
        mma_gemm_kernel<<<dim3(14, 128), 256, SMEM_MM>>>(FF_, D_, 10, 0, 2, 0, 2, l);
        mma_gemm_kernel<<<dim3(14, 128), 256, SMEM_MM>>>(FF_, D_, 10, 3, 2, 0, 3, l);
        mma_gemm_kernel<<<dim3(5, 128), 256, SMEM_MM>>>(D_, FF_, 27, 2, 1, 1, 4, l);
    }
    rmsnorm_kernel<<<TOK_, 128>>>(final_norm_w, out, nullptr);
}